// round 6
// baseline (speedup 1.0000x reference)
#include <cuda_runtime.h>
#include <cuda_bf16.h>
#include <cstdint>

// ---------------------------------------------------------------------------
// MobileAttention3D: B=2, C=256, D=32, H=W=32, NH=8, KD=VD=64
//
// R6: av on HMMA (+cvt_v), proj restructured M=256xN=64 (no X re-read),
//     qkv grid reordered for X L2-locality.
// bf16 2-term split (hi+lo), 3 MMAs per tile, fp32 accum.
// ---------------------------------------------------------------------------

#define NPOS 32768

__device__ float    g_V  [2*32*65536];    // [b][j][e*128+sig] (shuffled) fp32
__device__ float    g_Ap [64*16*1024];    // partial logits [fc][bn][i*32+j]
__device__ float    g_A  [16*1024];       // softmaxed attn
__device__ uint32_t g_xph[2*128*32768];   // x bf16-hi pairs [b][cp][p]
__device__ uint32_t g_xpl[2*128*32768];
__device__ uint32_t g_oph[2*256*32768];   // proj-input hi pairs [b][ep][p']
__device__ uint32_t g_opl[2*256*32768];
__device__ uint32_t g_wqh[128*640];       // qkv W hi pairs [kp][oc]
__device__ uint32_t g_wql[128*640];
__device__ uint32_t g_wph[256*256];       // proj W hi pairs [kp][oc]
__device__ uint32_t g_wpl[256*256];
__device__ uint32_t g_Qh [2*8*32*32768];  // Q hi pairs [(bn*32+i)][fp]
__device__ uint32_t g_Ql [2*8*32*32768];
__device__ uint32_t g_Kh [2*32*32768];    // K hi pairs [(b*32+j)][fp]
__device__ uint32_t g_Kl [2*32*32768];
__device__ uint32_t g_Vh [2*16*65536];    // V hi j-pairs [b][jp][f]
__device__ uint32_t g_Vl [2*16*65536];

// ---- helpers ----
__device__ __forceinline__ void pack2(float a, float b, uint32_t& hi, uint32_t& lo) {
    __nv_bfloat16 ah = __float2bfloat16(a), bh = __float2bfloat16(b);
    float ar = a - __bfloat162float(ah), br = b - __bfloat162float(bh);
    __nv_bfloat16 al = __float2bfloat16(ar), bl = __float2bfloat16(br);
    hi = (uint32_t)__bfloat16_as_ushort(ah) | ((uint32_t)__bfloat16_as_ushort(bh) << 16);
    lo = (uint32_t)__bfloat16_as_ushort(al) | ((uint32_t)__bfloat16_as_ushort(bl) << 16);
}

__device__ __forceinline__ uint32_t smem_u32(const void* p) {
    uint32_t a;
    asm("{ .reg .u64 t; cvta.to.shared.u64 t, %1; cvt.u32.u64 %0, t; }" : "=r"(a) : "l"(p));
    return a;
}

#define MMA16816(d, a, bf) \
    asm volatile("mma.sync.aligned.m16n8k16.row.col.f32.bf16.bf16.f32 " \
        "{%0,%1,%2,%3}, {%4,%5,%6,%7}, {%8,%9}, {%0,%1,%2,%3};" \
        : "+f"((d)[0]), "+f"((d)[1]), "+f"((d)[2]), "+f"((d)[3]) \
        : "r"((a)[0]), "r"((a)[1]), "r"((a)[2]), "r"((a)[3]), \
          "r"((bf)[0]), "r"((bf)[1]))

#define CP16(dst, src) \
    asm volatile("cp.async.cg.shared.global [%0], [%1], 16;" :: "r"(dst), "l"(src) : "memory")
#define CP_COMMIT() asm volatile("cp.async.commit_group;" ::: "memory")
#define CP_WAIT0()  asm volatile("cp.async.wait_group 0;" ::: "memory")

#define ROWW 136
#define AOFF (8*ROWW*4)
#define BUFOFF (4*AOFF)

// ---------------------------------------------------------------------------
// K0a: convert x to packed bf16 hi/lo pairs over adjacent channels.
// ---------------------------------------------------------------------------
__global__ __launch_bounds__(256) void cvt_x(const float* __restrict__ x)
{
    const int p  = blockIdx.x * 1024 + threadIdx.x * 4;
    const int cp = blockIdx.y;
    const int b  = blockIdx.z;
    const float4 x0 = *(const float4*)&x[((size_t)(b * 256 + 2*cp    ) << 15) + p];
    const float4 x1 = *(const float4*)&x[((size_t)(b * 256 + 2*cp + 1) << 15) + p];
    uint4 h, l;
    pack2(x0.x, x1.x, h.x, l.x);
    pack2(x0.y, x1.y, h.y, l.y);
    pack2(x0.z, x1.z, h.z, l.z);
    pack2(x0.w, x1.w, h.w, l.w);
    const size_t o = ((size_t)(b * 128 + cp) << 15) + p;
    *(uint4*)&g_xph[o] = h;
    *(uint4*)&g_xpl[o] = l;
}

// ---------------------------------------------------------------------------
// K0b: pre-pack weights (k-pair-major).
// ---------------------------------------------------------------------------
__global__ __launch_bounds__(256) void pack_w(
    const float* __restrict__ qw, const float* __restrict__ kvw,
    const float* __restrict__ pw)
{
    const int id = blockIdx.x * 256 + threadIdx.x;
    if (id < 128 * 640) {
        const int kp = id / 640, oc = id % 640;
        const float* wr = (oc < 512) ? qw + (size_t)oc * 256
                                     : kvw + (size_t)(oc - 512) * 256;
        uint32_t h, l;
        pack2(wr[2*kp], wr[2*kp + 1], h, l);
        g_wqh[id] = h; g_wql[id] = l;
    } else {
        const int id2 = id - 128 * 640;
        if (id2 < 256 * 256) {
            const int kp = id2 >> 8, oc = id2 & 255;
            uint32_t h, l;
            pack2(pw[(size_t)oc * 512 + 2*kp], pw[(size_t)oc * 512 + 2*kp + 1], h, l);
            g_wph[id2] = h; g_wpl[id2] = l;
        }
    }
}

// ---------------------------------------------------------------------------
// K0c (after qkv): pack V into bf16 hi/lo j-pairs [b][jp][f].
// ---------------------------------------------------------------------------
__global__ __launch_bounds__(256) void cvt_v()
{
    const int f  = blockIdx.x * 1024 + threadIdx.x * 4;
    const int jp = blockIdx.y;
    const int b  = blockIdx.z;
    const float4 v0 = *(const float4*)&g_V[((size_t)(b*32 + 2*jp    ) << 16) + f];
    const float4 v1 = *(const float4*)&g_V[((size_t)(b*32 + 2*jp + 1) << 16) + f];
    uint4 h, l;
    pack2(v0.x, v1.x, h.x, l.x);
    pack2(v0.y, v1.y, h.y, l.y);
    pack2(v0.z, v1.z, h.z, l.z);
    pack2(v0.w, v1.w, h.w, l.w);
    const size_t o = ((size_t)(b * 16 + jp) << 16) + f;
    *(uint4*)&g_Vh[o] = h;
    *(uint4*)&g_Vl[o] = l;
}

// ---------------------------------------------------------------------------
// qkv epilogue pair store.
// ---------------------------------------------------------------------------
__device__ __forceinline__ void store_pair(int b, int oc, int pos,
                                           float v0, float v1,
                                           const float* qb, const float* kvb)
{
    const int i = pos >> 10, s = pos & 1023, sp = s >> 1;
    if (oc < 512) {
        const float bias = qb[oc];
        uint32_t h, l;
        pack2(v0 + bias, v1 + bias, h, l);
        const size_t a = (size_t)((b*8 + (oc >> 6)) * 32 + i) * 32768 + (oc & 63) * 512 + sp;
        g_Qh[a] = h; g_Ql[a] = l;
    } else if (oc < 576) {
        const float bias = kvb[oc - 512];
        uint32_t h, l;
        pack2(v0 + bias, v1 + bias, h, l);
        const size_t a = (size_t)(b*32 + i) * 32768 + (oc - 512) * 512 + sp;
        g_Kh[a] = h; g_Kl[a] = l;
    } else {
        const float bias = kvb[oc - 512];
        const int cv = oc - 576;
        const int hh = s >> 5, w0 = s & 31;
        const int sigbase = ((hh >> 3) << 5) | ((hh & 7) << 2);
        const unsigned vb = ((unsigned)(b * 32 + i)) << 16;
        const int e20 = ((w0 & 7) << 6) | cv;
        const int e21 = (((w0 + 1) & 7) << 6) | cv;
        g_V[vb + (e20 << 7) + sigbase + (w0 >> 3)]       = v0 + bias;
        g_V[vb + (e21 << 7) + sigbase + ((w0 + 1) >> 3)] = v1 + bias;
    }
}

// ---------------------------------------------------------------------------
// Shared GEMM compute step (128oc x 128pos tiles; used by qkv).
// ---------------------------------------------------------------------------
__device__ __forceinline__ void gemm_step(
    const uint32_t* sm, int buf, int wm, int wn, int g, int t,
    float acc[4][4][4])
{
    const uint32_t* Awh = sm + (buf * 4 + 0) * 8 * ROWW;
    const uint32_t* Awl = sm + (buf * 4 + 1) * 8 * ROWW;
    const uint32_t* Bxh = sm + (buf * 4 + 2) * 8 * ROWW;
    const uint32_t* Bxl = sm + (buf * 4 + 3) * 8 * ROWW;

    uint32_t bh[4][2], bl[4][2];
#pragma unroll
    for (int nb = 0; nb < 4; nb++) {
        const int nbase = wn * 32 + nb * 8 + g;
        bh[nb][0] = Bxh[t * ROWW + nbase];       bh[nb][1] = Bxh[(t+4) * ROWW + nbase];
        bl[nb][0] = Bxl[t * ROWW + nbase];       bl[nb][1] = Bxl[(t+4) * ROWW + nbase];
    }
#pragma unroll
    for (int mb = 0; mb < 4; mb++) {
        const int mbase = wm * 64 + mb * 16 + g;
        uint32_t ah[4], al_[4];
        ah[0]  = Awh[t * ROWW + mbase];     ah[1]  = Awh[t * ROWW + mbase + 8];
        ah[2]  = Awh[(t+4) * ROWW + mbase]; ah[3]  = Awh[(t+4) * ROWW + mbase + 8];
        al_[0] = Awl[t * ROWW + mbase];     al_[1] = Awl[t * ROWW + mbase + 8];
        al_[2] = Awl[(t+4) * ROWW + mbase]; al_[3] = Awl[(t+4) * ROWW + mbase + 8];
#pragma unroll
        for (int nb = 0; nb < 4; nb++) {
            MMA16816(acc[mb][nb], ah,  bh[nb]);
            MMA16816(acc[mb][nb], ah,  bl[nb]);
            MMA16816(acc[mb][nb], al_, bh[nb]);
        }
    }
}

// ---------------------------------------------------------------------------
// K1: QKV GEMM. grid(5 mc, 256 p-tiles, 2 b) — mc fastest for X L2-locality.
// ---------------------------------------------------------------------------
__global__ __launch_bounds__(256) void qkv_mma(
    const float* __restrict__ qb, const float* __restrict__ kvb)
{
    __shared__ uint32_t sm[2 * 4 * 8 * ROWW];
    const int tid = threadIdx.x, lane = tid & 31, wid = tid >> 5;
    const int wm = wid & 1, wn = wid >> 1;
    const int g = lane >> 2, t = lane & 3;
    const int mc = blockIdx.x, p0 = blockIdx.y * 128, b = blockIdx.z;
    const uint32_t sbase = smem_u32(sm);

    const int r = tid >> 5, c4 = (tid & 31) * 4;
    const uint32_t dst0 = sbase + (r * ROWW + c4) * 4;

    float acc[4][4][4];
#pragma unroll
    for (int mb = 0; mb < 4; mb++)
#pragma unroll
        for (int nb = 0; nb < 4; nb++)
#pragma unroll
            for (int q = 0; q < 4; q++) acc[mb][nb][q] = 0.f;

    {
        const int wi = r * 640 + mc * 128 + c4;
        const size_t xi = ((size_t)(b * 128 + r) << 15) + p0 + c4;
        CP16(dst0,          &g_wqh[wi]);
        CP16(dst0 + AOFF,   &g_wql[wi]);
        CP16(dst0 + 2*AOFF, &g_xph[xi]);
        CP16(dst0 + 3*AOFF, &g_xpl[xi]);
        CP_COMMIT();
    }

    for (int s = 0; s < 16; s++) {
        CP_WAIT0();
        __syncthreads();
        if (s < 15) {
            const int sr = (s + 1) * 8 + r;
            const uint32_t d = dst0 + ((s + 1) & 1) * BUFOFF;
            const int wi = sr * 640 + mc * 128 + c4;
            const size_t xi = ((size_t)(b * 128 + sr) << 15) + p0 + c4;
            CP16(d,          &g_wqh[wi]);
            CP16(d + AOFF,   &g_wql[wi]);
            CP16(d + 2*AOFF, &g_xph[xi]);
            CP16(d + 3*AOFF, &g_xpl[xi]);
            CP_COMMIT();
        }
        gemm_step(sm, s & 1, wm, wn, g, t, acc);
    }

#pragma unroll
    for (int mb = 0; mb < 4; mb++) {
        const int oc_a = mc * 128 + wm * 64 + mb * 16 + g;
#pragma unroll
        for (int nb = 0; nb < 4; nb++) {
            const int pos_a = p0 + wn * 32 + nb * 8 + t * 2;
            store_pair(b, oc_a,     pos_a, acc[mb][nb][0], acc[mb][nb][1], qb, kvb);
            store_pair(b, oc_a + 8, pos_a, acc[mb][nb][2], acc[mb][nb][3], qb, kvb);
        }
    }
}

// ---------------------------------------------------------------------------
// K4: proj GEMM. Block = 256 ocs x 64 positions (no X re-read).
// grid(512 p-tiles of 64, 2 b), 256 thr (warps: 4 m x 2 n), K=512 (32 steps).
// ---------------------------------------------------------------------------
#define PWROW 264
#define PXROW 72
#define PW (8*PWROW)     // 2112 u32
#define PX (8*PXROW)     // 576 u32
#define PBUF (2*PW + 2*PX)
__global__ __launch_bounds__(256) void proj_mma(
    const float* __restrict__ pb, const float* __restrict__ ls,
    float* __restrict__ out)
{
    __shared__ uint32_t sm[2 * PBUF];    // 43 KB
    const int tid = threadIdx.x, lane = tid & 31, wid = tid >> 5;
    const int wm = wid & 3, wn = wid >> 2;
    const int g = lane >> 2, t = lane & 3;
    const int p0 = blockIdx.x * 64, b = blockIdx.y;
    const uint32_t sbase = smem_u32(sm);

    const int rW = tid >> 5, cW = (tid & 31) * 4;       // W: 8 rows x 256
    const int rX = tid >> 4, cX = (tid & 15) * 4;       // X: 8 rows x 64 (tid<128)

    float acc[4][4][4];
#pragma unroll
    for (int mb = 0; mb < 4; mb++)
#pragma unroll
        for (int nb = 0; nb < 4; nb++)
#pragma unroll
            for (int q = 0; q < 4; q++) acc[mb][nb][q] = 0.f;

    // prefetch s=0
    {
        const int kpW = rW;
        CP16(sbase + (rW*PWROW + cW)*4,            &g_wph[kpW*256 + cW]);
        CP16(sbase + (rW*PWROW + cW + 128)*4,      &g_wph[kpW*256 + cW + 128]);
        CP16(sbase + (PW + rW*PWROW + cW)*4,       &g_wpl[kpW*256 + cW]);
        CP16(sbase + (PW + rW*PWROW + cW + 128)*4, &g_wpl[kpW*256 + cW + 128]);
        if (tid < 128) {
            const size_t xi = ((size_t)(b * 256 + rX) << 15) + p0 + cX;
            CP16(sbase + (2*PW + rX*PXROW + cX)*4,      &g_oph[xi]);
            CP16(sbase + (2*PW + PX + rX*PXROW + cX)*4, &g_opl[xi]);
        }
        CP_COMMIT();
    }

    for (int s = 0; s < 32; s++) {
        CP_WAIT0();
        __syncthreads();
        if (s < 31) {
            const uint32_t d = sbase + (((s + 1) & 1) * PBUF) * 4;
            const int kpW = (s + 1) * 8 + rW;
            CP16(d + (rW*PWROW + cW)*4,            &g_wph[kpW*256 + cW]);
            CP16(d + (rW*PWROW + cW + 128)*4,      &g_wph[kpW*256 + cW + 128]);
            CP16(d + (PW + rW*PWROW + cW)*4,       &g_wpl[kpW*256 + cW]);
            CP16(d + (PW + rW*PWROW + cW + 128)*4, &g_wpl[kpW*256 + cW + 128]);
            if (tid < 128) {
                const int kpX = (s + 1) * 8 + rX;
                const size_t xi = ((size_t)(b * 256 + kpX) << 15) + p0 + cX;
                CP16(d + (2*PW + rX*PXROW + cX)*4,      &g_oph[xi]);
                CP16(d + (2*PW + PX + rX*PXROW + cX)*4, &g_opl[xi]);
            }
            CP_COMMIT();
        }
        // compute on buffer s&1
        const uint32_t* Wh = sm + (s & 1) * PBUF;
        const uint32_t* Wl = Wh + PW;
        const uint32_t* Xh = Wh + 2*PW;
        const uint32_t* Xl = Xh + PX;

        uint32_t bh[4][2], bl[4][2];
#pragma unroll
        for (int nb = 0; nb < 4; nb++) {
            const int nbase = wn * 32 + nb * 8 + g;
            bh[nb][0] = Xh[t * PXROW + nbase];   bh[nb][1] = Xh[(t+4) * PXROW + nbase];
            bl[nb][0] = Xl[t * PXROW + nbase];   bl[nb][1] = Xl[(t+4) * PXROW + nbase];
        }
#pragma unroll
        for (int mb = 0; mb < 4; mb++) {
            const int mbase = wm * 64 + mb * 16 + g;
            uint32_t ah[4], al_[4];
            ah[0]  = Wh[t * PWROW + mbase];     ah[1]  = Wh[t * PWROW + mbase + 8];
            ah[2]  = Wh[(t+4) * PWROW + mbase]; ah[3]  = Wh[(t+4) * PWROW + mbase + 8];
            al_[0] = Wl[t * PWROW + mbase];     al_[1] = Wl[t * PWROW + mbase + 8];
            al_[2] = Wl[(t+4) * PWROW + mbase]; al_[3] = Wl[(t+4) * PWROW + mbase + 8];
#pragma unroll
            for (int nb = 0; nb < 4; nb++) {
                MMA16816(acc[mb][nb], ah,  bh[nb]);
                MMA16816(acc[mb][nb], ah,  bl[nb]);
                MMA16816(acc[mb][nb], al_, bh[nb]);
            }
        }
    }

#pragma unroll
    for (int mb = 0; mb < 4; mb++) {
        const int r0 = wm * 64 + mb * 16 + g;
        const float b0 = pb[r0],     s0 = ls[r0];
        const float b1 = pb[r0 + 8], s1 = ls[r0 + 8];
#pragma unroll
        for (int nb = 0; nb < 4; nb++) {
            const int pos_a = p0 + wn * 32 + nb * 8 + t * 2;
            float* o0 = out + (((size_t)(b * 256 + r0)) << 15) + pos_a;
            float* o1 = out + (((size_t)(b * 256 + r0 + 8)) << 15) + pos_a;
            o0[0] = (acc[mb][nb][0] + b0) * s0;
            o0[1] = (acc[mb][nb][1] + b0) * s0;
            o1[0] = (acc[mb][nb][2] + b1) * s1;
            o1[1] = (acc[mb][nb][3] + b1) * s1;
        }
    }
}

// ---------------------------------------------------------------------------
// K2: scores via MMA. grid(64 fchunks, 16 bn), 128 thr.
// ---------------------------------------------------------------------------
#define SROW 36
__global__ __launch_bounds__(128) void scores_mma()
{
    __shared__ uint32_t sm[2 * 4 * 32 * SROW];
    const int tid = threadIdx.x, lane = tid & 31, w = tid >> 5;
    const int g = lane >> 2, t = lane & 3;
    const int fc = blockIdx.x, bn = blockIdx.y, b = bn >> 3;
    const uint32_t sbase = smem_u32(sm);

    const int r = tid >> 2, q = tid & 3;
    const size_t qrow = ((size_t)(bn * 32 + r)) * 32768 + fc * 512 + q * 8;
    const size_t krow = ((size_t)(b  * 32 + r)) * 32768 + fc * 512 + q * 8;
    const uint32_t dst0 = sbase + (r * SROW + q * 8) * 4;
    const uint32_t A1 = 32 * SROW * 4;

    float acc[2][4][4];
#pragma unroll
    for (int mi = 0; mi < 2; mi++)
#pragma unroll
        for (int ni = 0; ni < 4; ni++)
#pragma unroll
            for (int z = 0; z < 4; z++) acc[mi][ni][z] = 0.f;

    {
        CP16(dst0,        &g_Qh[qrow]);     CP16(dst0 + 16,        &g_Qh[qrow + 4]);
        CP16(dst0 + A1,   &g_Ql[qrow]);     CP16(dst0 + A1 + 16,   &g_Ql[qrow + 4]);
        CP16(dst0 + 2*A1, &g_Kh[krow]);     CP16(dst0 + 2*A1 + 16, &g_Kh[krow + 4]);
        CP16(dst0 + 3*A1, &g_Kl[krow]);     CP16(dst0 + 3*A1 + 16, &g_Kl[krow + 4]);
        CP_COMMIT();
    }

    for (int tl = 0; tl < 16; tl++) {
        CP_WAIT0();
        __syncthreads();
        if (tl < 15) {
            const uint32_t d = dst0 + ((tl + 1) & 1) * (4 * A1);
            const size_t qo = qrow + (tl + 1) * 32, ko = krow + (tl + 1) * 32;
            CP16(d,        &g_Qh[qo]);     CP16(d + 16,        &g_Qh[qo + 4]);
            CP16(d + A1,   &g_Ql[qo]);     CP16(d + A1 + 16,   &g_Ql[qo + 4]);
            CP16(d + 2*A1, &g_Kh[ko]);     CP16(d + 2*A1 + 16, &g_Kh[ko + 4]);
            CP16(d + 3*A1, &g_Kl[ko]);     CP16(d + 3*A1 + 16, &g_Kl[ko + 4]);
            CP_COMMIT();
        }
        const uint32_t* Qh = sm + ((tl & 1) * 4 + 0) * 32 * SROW;
        const uint32_t* Ql = sm + ((tl & 1) * 4 + 1) * 32 * SROW;
        const uint32_t* Kh = sm + ((tl & 1) * 4 + 2) * 32 * SROW;
        const uint32_t* Kl = sm + ((tl & 1) * 4 + 3) * 32 * SROW;
        const int kp = w * 8;

        uint32_t bh[4][2], bl[4][2];
#pragma unroll
        for (int ni = 0; ni < 4; ni++) {
            const int col = ni * 8 + g;
            bh[ni][0] = Kh[col * SROW + kp + t];
            bh[ni][1] = Kh[col * SROW + kp + t + 4];
            bl[ni][0] = Kl[col * SROW + kp + t];
            bl[ni][1] = Kl[col * SROW + kp + t + 4];
        }
#pragma unroll
        for (int mi = 0; mi < 2; mi++) {
            const int row = mi * 16 + g;
            uint32_t ah[4], al_[4];
            ah[0]  = Qh[row * SROW + kp + t];       ah[1]  = Qh[(row + 8) * SROW + kp + t];
            ah[2]  = Qh[row * SROW + kp + t + 4];   ah[3]  = Qh[(row + 8) * SROW + kp + t + 4];
            al_[0] = Ql[row * SROW + kp + t];       al_[1] = Ql[(row + 8) * SROW + kp + t];
            al_[2] = Ql[row * SROW + kp + t + 4];   al_[3] = Ql[(row + 8) * SROW + kp + t + 4];
#pragma unroll
            for (int ni = 0; ni < 4; ni++) {
                MMA16816(acc[mi][ni], ah,  bh[ni]);
                MMA16816(acc[mi][ni], ah,  bl[ni]);
                MMA16816(acc[mi][ni], al_, bh[ni]);
            }
        }
    }

    __syncthreads();
    float* red = (float*)sm;
#pragma unroll
    for (int mi = 0; mi < 2; mi++)
#pragma unroll
        for (int ni = 0; ni < 4; ni++) {
            const int i0 = mi * 16 + g, j0 = ni * 8 + t * 2;
            red[w * 1024 + i0 * 32 + j0]           = acc[mi][ni][0];
            red[w * 1024 + i0 * 32 + j0 + 1]       = acc[mi][ni][1];
            red[w * 1024 + (i0 + 8) * 32 + j0]     = acc[mi][ni][2];
            red[w * 1024 + (i0 + 8) * 32 + j0 + 1] = acc[mi][ni][3];
        }
    __syncthreads();
    const unsigned abase = (unsigned)(fc * 16 + bn) * 1024u;
#pragma unroll
    for (int e = 0; e < 8; e++) {
        const int idx = tid * 8 + e;
        g_Ap[abase + idx] = red[idx] + red[1024 + idx] + red[2048 + idx] + red[3072 + idx];
    }
}

// ---------------------------------------------------------------------------
__global__ __launch_bounds__(1024) void softmax_kernel()
{
    const int bn = blockIdx.x;
    const int tid = threadIdx.x;
    const int i = tid >> 5, j = tid & 31;
    float v = 0.f;
#pragma unroll
    for (int c = 0; c < 64; c++)
        v += g_Ap[((unsigned)(c * 16 + bn) << 10) + (i << 5) + j];
    v *= 0.125f;
    float m = v;
#pragma unroll
    for (int o = 16; o; o >>= 1) m = fmaxf(m, __shfl_xor_sync(0xffffffffu, m, o));
    float e = expf(v - m);
    float s = e;
#pragma unroll
    for (int o = 16; o; o >>= 1) s += __shfl_xor_sync(0xffffffffu, s, o);
    g_A[((unsigned)bn << 10) + (i << 5) + j] = e / s;
}

// ---------------------------------------------------------------------------
// K3: av via MMA. grid(32 f-tiles of 2048, 16 bn), 128 thr (4 warps).
// A (32x32 attn) lives in registers as bf16 hi/lo fragments.
// V streams in stages of 128 f (= one e channel); e-pair packing via pacc regs.
// ---------------------------------------------------------------------------
#define VROW 136
#define VHB (16*VROW)        // u32 per array
__global__ __launch_bounds__(128) void av_mma()
{
    __shared__ uint32_t sm[2 * 2 * VHB];   // [buf][h/l][16][136] = 34.8 KB
    const int tid = threadIdx.x, lane = tid & 31, w = tid >> 5;
    const int g = lane >> 2, t = lane & 3;
    const int bn = blockIdx.y, b = bn >> 3, n = bn & 7;
    const int f0 = blockIdx.x * 2048;
    const uint32_t sbase = smem_u32(sm);

    // Build A fragments (attn is tiny; L2-hot)
    const float* A = g_A + (bn << 10);
    uint32_t ah[2][2][4], al[2][2][4];
#pragma unroll
    for (int mf = 0; mf < 2; mf++)
#pragma unroll
        for (int kf = 0; kf < 2; kf++) {
            const int r0 = mf * 16 + g, r1 = r0 + 8;
            const int c0 = kf * 16 + 2 * t, c1 = c0 + 8;
            pack2(A[r0*32 + c0], A[r0*32 + c0 + 1], ah[mf][kf][0], al[mf][kf][0]);
            pack2(A[r1*32 + c0], A[r1*32 + c0 + 1], ah[mf][kf][1], al[mf][kf][1]);
            pack2(A[r0*32 + c1], A[r0*32 + c1 + 1], ah[mf][kf][2], al[mf][kf][2]);
            pack2(A[r1*32 + c1], A[r1*32 + c1 + 1], ah[mf][kf][3], al[mf][kf][3]);
        }

    // stage loads: thread -> row r (16), col chunks cq + 32q
    const int r = tid >> 3, cq = (tid & 7) * 4;
    const size_t vrow = ((size_t)(b * 16 + r) << 16) + f0;

    // prefetch stage 0
#pragma unroll
    for (int q2 = 0; q2 < 4; q2++) {
        const int col = cq + 32 * q2;
        CP16(sbase + (r * VROW + col) * 4,         &g_Vh[vrow + col]);
        CP16(sbase + (VHB + r * VROW + col) * 4,   &g_Vl[vrow + col]);
    }
    CP_COMMIT();

    float pacc[2][4][4];
    for (int s = 0; s < 16; s++) {
        CP_WAIT0();
        __syncthreads();
        if (s < 15) {
            const uint32_t d = sbase + (((s + 1) & 1) * 2 * VHB) * 4;
            const size_t vo = vrow + (s + 1) * 128;
#pragma unroll
            for (int q2 = 0; q2 < 4; q2++) {
                const int col = cq + 32 * q2;
                CP16(d + (r * VROW + col) * 4,       &g_Vh[vo + col]);
                CP16(d + (VHB + r * VROW + col) * 4, &g_Vl[vo + col]);
            }
            CP_COMMIT();
        }
        const uint32_t* Vh = sm + (s & 1) * 2 * VHB;
        const uint32_t* Vl = Vh + VHB;

        float acc[2][4][4];
#pragma unroll
        for (int mf = 0; mf < 2; mf++)
#pragma unroll
            for (int nb = 0; nb < 4; nb++)
#pragma unroll
                for (int z = 0; z < 4; z++) acc[mf][nb][z] = 0.f;

#pragma unroll
        for (int kf = 0; kf < 2; kf++) {
            uint32_t bh[4][2], bl[4][2];
#pragma unroll
            for (int nb = 0; nb < 4; nb++) {
                const int col = w * 32 + nb * 8 + g;
                bh[nb][0] = Vh[(kf*8 + t)     * VROW + col];
                bh[nb][1] = Vh[(kf*8 + t + 4) * VROW + col];
                bl[nb][0] = Vl[(kf*8 + t)     * VROW + col];
                bl[nb][1] = Vl[(kf*8 + t + 4) * VROW + col];
            }
#pragma unroll
            for (int mf = 0; mf < 2; mf++)
#pragma unroll
                for (int nb = 0; nb < 4; nb++) {
                    MMA16816(acc[mf][nb], ah[mf][kf], bh[nb]);
                    MMA16816(acc[mf][nb], ah[mf][kf], bl[nb]);
                    MMA16816(acc[mf][nb], al[mf][kf], bh[nb]);
                }
        }

        if ((s & 1) == 0) {
#pragma unroll
            for (int mf = 0; mf < 2; mf++)
#pragma unroll
                for (int nb = 0; nb < 4; nb++)
#pragma unroll
                    for (int z = 0; z < 4; z++) pacc[mf][nb][z] = acc[mf][nb][z];
        } else {
            const int ep = blockIdx.x * 8 + (s >> 1);
            const size_t obase = ((size_t)(b * 256 + ep) << 15) + (n << 7);
#pragma unroll
            for (int mf = 0; mf < 2; mf++)
#pragma unroll
                for (int nb = 0; nb < 4; nb++) {
                    const int sig = w * 32 + nb * 8 + 2 * t;
                    const int row0 = mf * 16 + g, row1 = row0 + 8;
                    uint32_t h, l;
                    pack2(pacc[mf][nb][0], acc[mf][nb][0], h, l);
                    g_oph[obase + (row0 << 10) + sig]     = h;
                    g_opl[obase + (row0 << 10) + sig]     = l;
                    pack2(pacc[mf][nb][1], acc[mf][nb][1], h, l);
                    g_oph[obase + (row0 << 10) + sig + 1] = h;
                    g_opl[obase + (row0 << 10) + sig + 1] = l;
                    pack2(pacc[mf][nb][2], acc[mf][nb][2], h, l);
                    g_oph[obase + (row1 << 10) + sig]     = h;
                    g_opl[obase + (row1 << 10) + sig]     = l;
                    pack2(pacc[mf][nb][3], acc[mf][nb][3], h, l);
                    g_oph[obase + (row1 << 10) + sig + 1] = h;
                    g_opl[obase + (row1 << 10) + sig + 1] = l;
                }
        }
    }
}

// ---------------------------------------------------------------------------
extern "C" void kernel_launch(void* const* d_in, const int* in_sizes, int n_in,
                              void* d_out, int out_size)
{
    (void)in_sizes; (void)n_in; (void)out_size;
    const float* x   = (const float*)d_in[0];
    const float* qw  = (const float*)d_in[1];
    const float* qb  = (const float*)d_in[2];
    const float* kvw = (const float*)d_in[3];
    const float* kvb = (const float*)d_in[4];
    const float* pw  = (const float*)d_in[5];
    const float* pb  = (const float*)d_in[6];
    const float* ls  = (const float*)d_in[7];
    float* out = (float*)d_out;

    pack_w        <<<576, 256>>>(qw, kvw, pw);
    cvt_x         <<<dim3(32, 128, 2), 256>>>(x);
    qkv_mma       <<<dim3(5, 256, 2), 256>>>(qb, kvb);
    cvt_v         <<<dim3(64, 16, 2), 256>>>();
    scores_mma    <<<dim3(64, 16), 128>>>();
    softmax_kernel<<<16, 1024>>>();
    av_mma        <<<dim3(32, 16), 128>>>();
    proj_mma      <<<dim3(512, 2), 256>>>(pb, ls, out);
}

// round 8
// speedup vs baseline: 1.3703x; 1.3703x over previous
#include <cuda_runtime.h>
#include <cuda_bf16.h>
#include <cstdint>

// ---------------------------------------------------------------------------
// MobileAttention3D: B=2, C=256, D=32, H=W=32, NH=8, KD=VD=64
//
// R7 = R5 (last known-good, 535us) + grid reorders only:
//   qkv: mc fastest-varying  -> X stream read ~1x instead of 5x (L2 share)
//   proj: mc fastest-varying -> oph/opl stream read ~1x instead of 2x
// bf16 2-term split (hi+lo), 3 MMAs per tile, fp32 accum.
// ---------------------------------------------------------------------------

#define NPOS 32768

__device__ float    g_V  [2*32*65536];    // [b][j][e][sigma] (shuffled)
__device__ float    g_Ap [64*16*1024];    // partial logits [fc][bn][i*32+j]
__device__ float    g_A  [16*1024];       // softmaxed attn
__device__ uint32_t g_xph[2*128*32768];   // x bf16-hi pairs [b][cp][p]
__device__ uint32_t g_xpl[2*128*32768];
__device__ uint32_t g_oph[2*256*32768];   // proj-input hi pairs [b][ep][p']
__device__ uint32_t g_opl[2*256*32768];
__device__ uint32_t g_wqh[128*640];       // qkv W hi pairs [kp][oc]
__device__ uint32_t g_wql[128*640];
__device__ uint32_t g_wph[256*256];       // proj W hi pairs [kp][oc]
__device__ uint32_t g_wpl[256*256];
__device__ uint32_t g_Qh [2*8*32*32768];  // Q hi pairs [(bn*32+i)][fp]
__device__ uint32_t g_Ql [2*8*32*32768];
__device__ uint32_t g_Kh [2*32*32768];    // K hi pairs [(b*32+j)][fp]
__device__ uint32_t g_Kl [2*32*32768];

// ---- helpers ----
__device__ __forceinline__ void pack2(float a, float b, uint32_t& hi, uint32_t& lo) {
    __nv_bfloat16 ah = __float2bfloat16(a), bh = __float2bfloat16(b);
    float ar = a - __bfloat162float(ah), br = b - __bfloat162float(bh);
    __nv_bfloat16 al = __float2bfloat16(ar), bl = __float2bfloat16(br);
    hi = (uint32_t)__bfloat16_as_ushort(ah) | ((uint32_t)__bfloat16_as_ushort(bh) << 16);
    lo = (uint32_t)__bfloat16_as_ushort(al) | ((uint32_t)__bfloat16_as_ushort(bl) << 16);
}

__device__ __forceinline__ uint32_t smem_u32(const void* p) {
    uint32_t a;
    asm("{ .reg .u64 t; cvta.to.shared.u64 t, %1; cvt.u32.u64 %0, t; }" : "=r"(a) : "l"(p));
    return a;
}

#define MMA16816(d, a, bf) \
    asm volatile("mma.sync.aligned.m16n8k16.row.col.f32.bf16.bf16.f32 " \
        "{%0,%1,%2,%3}, {%4,%5,%6,%7}, {%8,%9}, {%0,%1,%2,%3};" \
        : "+f"((d)[0]), "+f"((d)[1]), "+f"((d)[2]), "+f"((d)[3]) \
        : "r"((a)[0]), "r"((a)[1]), "r"((a)[2]), "r"((a)[3]), \
          "r"((bf)[0]), "r"((bf)[1]))

#define CP16(dst, src) \
    asm volatile("cp.async.cg.shared.global [%0], [%1], 16;" :: "r"(dst), "l"(src) : "memory")
#define CP_COMMIT() asm volatile("cp.async.commit_group;" ::: "memory")
#define CP_WAIT0()  asm volatile("cp.async.wait_group 0;" ::: "memory")

#define ROWW 136
#define AOFF (8*ROWW*4)
#define BUFOFF (4*AOFF)

// ---------------------------------------------------------------------------
// K0a: convert x to packed bf16 hi/lo pairs over adjacent channels.
// ---------------------------------------------------------------------------
__global__ __launch_bounds__(256) void cvt_x(const float* __restrict__ x)
{
    const int p  = blockIdx.x * 1024 + threadIdx.x * 4;
    const int cp = blockIdx.y;
    const int b  = blockIdx.z;
    const float4 x0 = *(const float4*)&x[((size_t)(b * 256 + 2*cp    ) << 15) + p];
    const float4 x1 = *(const float4*)&x[((size_t)(b * 256 + 2*cp + 1) << 15) + p];
    uint4 h, l;
    pack2(x0.x, x1.x, h.x, l.x);
    pack2(x0.y, x1.y, h.y, l.y);
    pack2(x0.z, x1.z, h.z, l.z);
    pack2(x0.w, x1.w, h.w, l.w);
    const size_t o = ((size_t)(b * 128 + cp) << 15) + p;
    *(uint4*)&g_xph[o] = h;
    *(uint4*)&g_xpl[o] = l;
}

// ---------------------------------------------------------------------------
// K0b: pre-pack weights (k-pair-major).
// ---------------------------------------------------------------------------
__global__ __launch_bounds__(256) void pack_w(
    const float* __restrict__ qw, const float* __restrict__ kvw,
    const float* __restrict__ pw)
{
    const int id = blockIdx.x * 256 + threadIdx.x;
    if (id < 128 * 640) {
        const int kp = id / 640, oc = id % 640;
        const float* wr = (oc < 512) ? qw + (size_t)oc * 256
                                     : kvw + (size_t)(oc - 512) * 256;
        uint32_t h, l;
        pack2(wr[2*kp], wr[2*kp + 1], h, l);
        g_wqh[id] = h; g_wql[id] = l;
    } else {
        const int id2 = id - 128 * 640;
        if (id2 < 256 * 256) {
            const int kp = id2 >> 8, oc = id2 & 255;
            uint32_t h, l;
            pack2(pw[(size_t)oc * 512 + 2*kp], pw[(size_t)oc * 512 + 2*kp + 1], h, l);
            g_wph[id2] = h; g_wpl[id2] = l;
        }
    }
}

// ---------------------------------------------------------------------------
// qkv epilogue pair store: (oc, pos even) + (oc, pos+1).
// ---------------------------------------------------------------------------
__device__ __forceinline__ void store_pair(int b, int oc, int pos,
                                           float v0, float v1,
                                           const float* qb, const float* kvb)
{
    const int i = pos >> 10, s = pos & 1023, sp = s >> 1;
    if (oc < 512) {
        const float bias = qb[oc];
        uint32_t h, l;
        pack2(v0 + bias, v1 + bias, h, l);
        const size_t a = (size_t)((b*8 + (oc >> 6)) * 32 + i) * 32768 + (oc & 63) * 512 + sp;
        g_Qh[a] = h; g_Ql[a] = l;
    } else if (oc < 576) {
        const float bias = kvb[oc - 512];
        uint32_t h, l;
        pack2(v0 + bias, v1 + bias, h, l);
        const size_t a = (size_t)(b*32 + i) * 32768 + (oc - 512) * 512 + sp;
        g_Kh[a] = h; g_Kl[a] = l;
    } else {
        const float bias = kvb[oc - 512];
        const int cv = oc - 576;
        const int hh = s >> 5, w0 = s & 31;          // s even -> same h for s+1
        const int sigbase = ((hh >> 3) << 5) | ((hh & 7) << 2);
        const unsigned vb = ((unsigned)(b * 32 + i)) << 16;
        const int e20 = ((w0 & 7) << 6) | cv;
        const int e21 = (((w0 + 1) & 7) << 6) | cv;
        g_V[vb + (e20 << 7) + sigbase + (w0 >> 3)]       = v0 + bias;
        g_V[vb + (e21 << 7) + sigbase + ((w0 + 1) >> 3)] = v1 + bias;
    }
}

// ---------------------------------------------------------------------------
// Shared GEMM compute step (reads one smem buffer, 3-term split MMA).
// ---------------------------------------------------------------------------
__device__ __forceinline__ void gemm_step(
    const uint32_t* sm, int buf, int wm, int wn, int g, int t,
    float acc[4][4][4])
{
    const uint32_t* Awh = sm + (buf * 4 + 0) * 8 * ROWW;
    const uint32_t* Awl = sm + (buf * 4 + 1) * 8 * ROWW;
    const uint32_t* Bxh = sm + (buf * 4 + 2) * 8 * ROWW;
    const uint32_t* Bxl = sm + (buf * 4 + 3) * 8 * ROWW;

    uint32_t bh[4][2], bl[4][2];
#pragma unroll
    for (int nb = 0; nb < 4; nb++) {
        const int nbase = wn * 32 + nb * 8 + g;
        bh[nb][0] = Bxh[t * ROWW + nbase];       bh[nb][1] = Bxh[(t+4) * ROWW + nbase];
        bl[nb][0] = Bxl[t * ROWW + nbase];       bl[nb][1] = Bxl[(t+4) * ROWW + nbase];
    }
#pragma unroll
    for (int mb = 0; mb < 4; mb++) {
        const int mbase = wm * 64 + mb * 16 + g;
        uint32_t ah[4], al_[4];
        ah[0]  = Awh[t * ROWW + mbase];     ah[1]  = Awh[t * ROWW + mbase + 8];
        ah[2]  = Awh[(t+4) * ROWW + mbase]; ah[3]  = Awh[(t+4) * ROWW + mbase + 8];
        al_[0] = Awl[t * ROWW + mbase];     al_[1] = Awl[t * ROWW + mbase + 8];
        al_[2] = Awl[(t+4) * ROWW + mbase]; al_[3] = Awl[(t+4) * ROWW + mbase + 8];
#pragma unroll
        for (int nb = 0; nb < 4; nb++) {
            MMA16816(acc[mb][nb], ah,  bh[nb]);
            MMA16816(acc[mb][nb], ah,  bl[nb]);
            MMA16816(acc[mb][nb], al_, bh[nb]);
        }
    }
}

// ---------------------------------------------------------------------------
// K1: QKV GEMM. grid(5 mc, 256 p-tiles, 2 b) — mc fastest: X L2 sharing.
// ---------------------------------------------------------------------------
__global__ __launch_bounds__(256) void qkv_mma(
    const float* __restrict__ qb, const float* __restrict__ kvb)
{
    __shared__ uint32_t sm[2 * 4 * 8 * ROWW];
    const int tid = threadIdx.x, lane = tid & 31, wid = tid >> 5;
    const int wm = wid & 1, wn = wid >> 1;
    const int g = lane >> 2, t = lane & 3;
    const int mc = blockIdx.x, p0 = blockIdx.y * 128, b = blockIdx.z;
    const uint32_t sbase = smem_u32(sm);

    const int r = tid >> 5, c4 = (tid & 31) * 4;
    const uint32_t dst0 = sbase + (r * ROWW + c4) * 4;

    float acc[4][4][4];
#pragma unroll
    for (int mb = 0; mb < 4; mb++)
#pragma unroll
        for (int nb = 0; nb < 4; nb++)
#pragma unroll
            for (int q = 0; q < 4; q++) acc[mb][nb][q] = 0.f;

    {
        const int wi = r * 640 + mc * 128 + c4;
        const size_t xi = ((size_t)(b * 128 + r) << 15) + p0 + c4;
        CP16(dst0,          &g_wqh[wi]);
        CP16(dst0 + AOFF,   &g_wql[wi]);
        CP16(dst0 + 2*AOFF, &g_xph[xi]);
        CP16(dst0 + 3*AOFF, &g_xpl[xi]);
        CP_COMMIT();
    }

    for (int s = 0; s < 16; s++) {
        CP_WAIT0();
        __syncthreads();
        if (s < 15) {
            const int sr = (s + 1) * 8 + r;
            const uint32_t d = dst0 + ((s + 1) & 1) * BUFOFF;
            const int wi = sr * 640 + mc * 128 + c4;
            const size_t xi = ((size_t)(b * 128 + sr) << 15) + p0 + c4;
            CP16(d,          &g_wqh[wi]);
            CP16(d + AOFF,   &g_wql[wi]);
            CP16(d + 2*AOFF, &g_xph[xi]);
            CP16(d + 3*AOFF, &g_xpl[xi]);
            CP_COMMIT();
        }
        gemm_step(sm, s & 1, wm, wn, g, t, acc);
    }

#pragma unroll
    for (int mb = 0; mb < 4; mb++) {
        const int oc_a = mc * 128 + wm * 64 + mb * 16 + g;
#pragma unroll
        for (int nb = 0; nb < 4; nb++) {
            const int pos_a = p0 + wn * 32 + nb * 8 + t * 2;
            store_pair(b, oc_a,     pos_a, acc[mb][nb][0], acc[mb][nb][1], qb, kvb);
            store_pair(b, oc_a + 8, pos_a, acc[mb][nb][2], acc[mb][nb][3], qb, kvb);
        }
    }
}

// ---------------------------------------------------------------------------
// K4: proj GEMM. grid(2 mc, 256 p-tiles, 2 b) — mc fastest: X L2 sharing.
// ---------------------------------------------------------------------------
__global__ __launch_bounds__(256) void proj_mma(
    const float* __restrict__ pb, const float* __restrict__ ls,
    float* __restrict__ out)
{
    __shared__ uint32_t sm[2 * 4 * 8 * ROWW];
    const int tid = threadIdx.x, lane = tid & 31, wid = tid >> 5;
    const int wm = wid & 1, wn = wid >> 1;
    const int g = lane >> 2, t = lane & 3;
    const int mc = blockIdx.x, p0 = blockIdx.y * 128, b = blockIdx.z;
    const uint32_t sbase = smem_u32(sm);

    const int r = tid >> 5, c4 = (tid & 31) * 4;
    const uint32_t dst0 = sbase + (r * ROWW + c4) * 4;

    float acc[4][4][4];
#pragma unroll
    for (int mb = 0; mb < 4; mb++)
#pragma unroll
        for (int nb = 0; nb < 4; nb++)
#pragma unroll
            for (int q = 0; q < 4; q++) acc[mb][nb][q] = 0.f;

    {
        const int wi = r * 256 + mc * 128 + c4;
        const size_t xi = ((size_t)(b * 256 + r) << 15) + p0 + c4;
        CP16(dst0,          &g_wph[wi]);
        CP16(dst0 + AOFF,   &g_wpl[wi]);
        CP16(dst0 + 2*AOFF, &g_oph[xi]);
        CP16(dst0 + 3*AOFF, &g_opl[xi]);
        CP_COMMIT();
    }

    for (int s = 0; s < 32; s++) {
        CP_WAIT0();
        __syncthreads();
        if (s < 31) {
            const int sr = (s + 1) * 8 + r;
            const uint32_t d = dst0 + ((s + 1) & 1) * BUFOFF;
            const int wi = sr * 256 + mc * 128 + c4;
            const size_t xi = ((size_t)(b * 256 + sr) << 15) + p0 + c4;
            CP16(d,          &g_wph[wi]);
            CP16(d + AOFF,   &g_wpl[wi]);
            CP16(d + 2*AOFF, &g_oph[xi]);
            CP16(d + 3*AOFF, &g_opl[xi]);
            CP_COMMIT();
        }
        gemm_step(sm, s & 1, wm, wn, g, t, acc);
    }

#pragma unroll
    for (int mb = 0; mb < 4; mb++) {
        const int r0 = mc * 128 + wm * 64 + mb * 16 + g;
        const float b0 = pb[r0],     s0 = ls[r0];
        const float b1 = pb[r0 + 8], s1 = ls[r0 + 8];
#pragma unroll
        for (int nb = 0; nb < 4; nb++) {
            const int pos_a = p0 + wn * 32 + nb * 8 + t * 2;
            float* o0 = out + (((size_t)(b * 256 + r0)) << 15) + pos_a;
            float* o1 = out + (((size_t)(b * 256 + r0 + 8)) << 15) + pos_a;
            o0[0] = (acc[mb][nb][0] + b0) * s0;
            o0[1] = (acc[mb][nb][1] + b0) * s0;
            o1[0] = (acc[mb][nb][2] + b1) * s1;
            o1[1] = (acc[mb][nb][3] + b1) * s1;
        }
    }
}

// ---------------------------------------------------------------------------
// K2: scores via MMA. grid(64 fchunks, 16 bn), 128 thr (4 warps, f-split).
// ---------------------------------------------------------------------------
#define SROW 36
__global__ __launch_bounds__(128) void scores_mma()
{
    __shared__ uint32_t sm[2 * 4 * 32 * SROW];   // 36864 B
    const int tid = threadIdx.x, lane = tid & 31, w = tid >> 5;
    const int g = lane >> 2, t = lane & 3;
    const int fc = blockIdx.x, bn = blockIdx.y, b = bn >> 3;
    const uint32_t sbase = smem_u32(sm);

    const int r = tid >> 2, q = tid & 3;
    const size_t qrow = ((size_t)(bn * 32 + r)) * 32768 + fc * 512 + q * 8;
    const size_t krow = ((size_t)(b  * 32 + r)) * 32768 + fc * 512 + q * 8;
    const uint32_t dst0 = sbase + (r * SROW + q * 8) * 4;
    const uint32_t A1 = 32 * SROW * 4;

    float acc[2][4][4];
#pragma unroll
    for (int mi = 0; mi < 2; mi++)
#pragma unroll
        for (int ni = 0; ni < 4; ni++)
#pragma unroll
            for (int z = 0; z < 4; z++) acc[mi][ni][z] = 0.f;

    {
        CP16(dst0,        &g_Qh[qrow]);     CP16(dst0 + 16,        &g_Qh[qrow + 4]);
        CP16(dst0 + A1,   &g_Ql[qrow]);     CP16(dst0 + A1 + 16,   &g_Ql[qrow + 4]);
        CP16(dst0 + 2*A1, &g_Kh[krow]);     CP16(dst0 + 2*A1 + 16, &g_Kh[krow + 4]);
        CP16(dst0 + 3*A1, &g_Kl[krow]);     CP16(dst0 + 3*A1 + 16, &g_Kl[krow + 4]);
        CP_COMMIT();
    }

    for (int tl = 0; tl < 16; tl++) {
        CP_WAIT0();
        __syncthreads();
        if (tl < 15) {
            const uint32_t d = dst0 + ((tl + 1) & 1) * (4 * A1);
            const size_t qo = qrow + (tl + 1) * 32, ko = krow + (tl + 1) * 32;
            CP16(d,        &g_Qh[qo]);     CP16(d + 16,        &g_Qh[qo + 4]);
            CP16(d + A1,   &g_Ql[qo]);     CP16(d + A1 + 16,   &g_Ql[qo + 4]);
            CP16(d + 2*A1, &g_Kh[ko]);     CP16(d + 2*A1 + 16, &g_Kh[ko + 4]);
            CP16(d + 3*A1, &g_Kl[ko]);     CP16(d + 3*A1 + 16, &g_Kl[ko + 4]);
            CP_COMMIT();
        }
        const uint32_t* Qh = sm + ((tl & 1) * 4 + 0) * 32 * SROW;
        const uint32_t* Ql = sm + ((tl & 1) * 4 + 1) * 32 * SROW;
        const uint32_t* Kh = sm + ((tl & 1) * 4 + 2) * 32 * SROW;
        const uint32_t* Kl = sm + ((tl & 1) * 4 + 3) * 32 * SROW;
        const int kp = w * 8;

        uint32_t bh[4][2], bl[4][2];
#pragma unroll
        for (int ni = 0; ni < 4; ni++) {
            const int col = ni * 8 + g;
            bh[ni][0] = Kh[col * SROW + kp + t];
            bh[ni][1] = Kh[col * SROW + kp + t + 4];
            bl[ni][0] = Kl[col * SROW + kp + t];
            bl[ni][1] = Kl[col * SROW + kp + t + 4];
        }
#pragma unroll
        for (int mi = 0; mi < 2; mi++) {
            const int row = mi * 16 + g;
            uint32_t ah[4], al_[4];
            ah[0]  = Qh[row * SROW + kp + t];       ah[1]  = Qh[(row + 8) * SROW + kp + t];
            ah[2]  = Qh[row * SROW + kp + t + 4];   ah[3]  = Qh[(row + 8) * SROW + kp + t + 4];
            al_[0] = Ql[row * SROW + kp + t];       al_[1] = Ql[(row + 8) * SROW + kp + t];
            al_[2] = Ql[row * SROW + kp + t + 4];   al_[3] = Ql[(row + 8) * SROW + kp + t + 4];
#pragma unroll
            for (int ni = 0; ni < 4; ni++) {
                MMA16816(acc[mi][ni], ah,  bh[ni]);
                MMA16816(acc[mi][ni], ah,  bl[ni]);
                MMA16816(acc[mi][ni], al_, bh[ni]);
            }
        }
    }

    __syncthreads();
    float* red = (float*)sm;
#pragma unroll
    for (int mi = 0; mi < 2; mi++)
#pragma unroll
        for (int ni = 0; ni < 4; ni++) {
            const int i0 = mi * 16 + g, j0 = ni * 8 + t * 2;
            red[w * 1024 + i0 * 32 + j0]           = acc[mi][ni][0];
            red[w * 1024 + i0 * 32 + j0 + 1]       = acc[mi][ni][1];
            red[w * 1024 + (i0 + 8) * 32 + j0]     = acc[mi][ni][2];
            red[w * 1024 + (i0 + 8) * 32 + j0 + 1] = acc[mi][ni][3];
        }
    __syncthreads();
    const unsigned abase = (unsigned)(fc * 16 + bn) * 1024u;
#pragma unroll
    for (int e = 0; e < 8; e++) {
        const int idx = tid * 8 + e;
        g_Ap[abase + idx] = red[idx] + red[1024 + idx] + red[2048 + idx] + red[3072 + idx];
    }
}

// ---------------------------------------------------------------------------
__global__ __launch_bounds__(1024) void softmax_kernel()
{
    const int bn = blockIdx.x;
    const int tid = threadIdx.x;
    const int i = tid >> 5, j = tid & 31;
    float v = 0.f;
#pragma unroll
    for (int c = 0; c < 64; c++)
        v += g_Ap[((unsigned)(c * 16 + bn) << 10) + (i << 5) + j];
    v *= 0.125f;
    float m = v;
#pragma unroll
    for (int o = 16; o; o >>= 1) m = fmaxf(m, __shfl_xor_sync(0xffffffffu, m, o));
    float e = expf(v - m);
    float s = e;
#pragma unroll
    for (int o = 16; o; o >>= 1) s += __shfl_xor_sync(0xffffffffu, s, o);
    g_A[((unsigned)bn << 10) + (i << 5) + j] = e / s;
}

// ---------------------------------------------------------------------------
// K3: O' = A @ V'. Writes proj input as packed bf16 hi/lo pairs (coalesced).
// ---------------------------------------------------------------------------
__global__ __launch_bounds__(256) void av_kernel()
{
    __shared__ __align__(16) float As[1024];
    __shared__ float Vs[2][32][128];
    const int tid = threadIdx.x;
    const int bn = blockIdx.y;
    const int b = bn >> 3, n = bn & 7;
    const int e0 = blockIdx.x * 16;

#pragma unroll
    for (int l = 0; l < 4; l++)
        As[l * 256 + tid] = g_A[((unsigned)bn << 10) + l * 256 + tid];
    __syncthreads();

    const int eh  = tid >> 7;
    const int sig = tid & 127;
    const unsigned vbase = ((unsigned)(b * 32)) << 16;

    for (int ei = 0; ei < 16; ei += 2) {
        const int e = e0 + ei + eh;
#pragma unroll
        for (int j = 0; j < 32; j++)
            Vs[eh][j][sig] = g_V[vbase + ((unsigned)j << 16) + (e << 7) + sig];
        __syncthreads();

        float v[32];
#pragma unroll
        for (int j = 0; j < 32; j++) v[j] = Vs[eh][j][sig];

        float acc[32];
#pragma unroll
        for (int i = 0; i < 32; i++) acc[i] = 0.f;
#pragma unroll
        for (int i = 0; i < 32; i++) {
#pragma unroll
            for (int j4 = 0; j4 < 8; j4++) {
                const float4 a = *(const float4*)&As[(i << 5) + j4 * 4];
                acc[i] += a.x * v[j4*4] + a.y * v[j4*4+1] + a.z * v[j4*4+2] + a.w * v[j4*4+3];
            }
        }
        __syncthreads();
#pragma unroll
        for (int i = 0; i < 32; i++) Vs[eh][i][sig] = acc[i];
        __syncthreads();

        const int ep = (e0 + ei) >> 1;
        const size_t obase = ((size_t)(b * 256 + ep) << 15) + (n << 7) + sig;
#pragma unroll
        for (int ii = 0; ii < 16; ii++) {
            const int i = eh * 16 + ii;
            uint32_t h, l;
            pack2(Vs[0][i][sig], Vs[1][i][sig], h, l);
            g_oph[obase + ((size_t)i << 10)] = h;
            g_opl[obase + ((size_t)i << 10)] = l;
        }
        __syncthreads();
    }
}

// ---------------------------------------------------------------------------
extern "C" void kernel_launch(void* const* d_in, const int* in_sizes, int n_in,
                              void* d_out, int out_size)
{
    (void)in_sizes; (void)n_in; (void)out_size;
    const float* x   = (const float*)d_in[0];
    const float* qw  = (const float*)d_in[1];
    const float* qb  = (const float*)d_in[2];
    const float* kvw = (const float*)d_in[3];
    const float* kvb = (const float*)d_in[4];
    const float* pw  = (const float*)d_in[5];
    const float* pb  = (const float*)d_in[6];
    const float* ls  = (const float*)d_in[7];
    float* out = (float*)d_out;

    pack_w        <<<576, 256>>>(qw, kvw, pw);
    cvt_x         <<<dim3(32, 128, 2), 256>>>(x);
    qkv_mma       <<<dim3(5, 256, 2), 256>>>(qb, kvb);
    scores_mma    <<<dim3(64, 16), 128>>>();
    softmax_kernel<<<16, 1024>>>();
    av_kernel     <<<dim3(32, 16), 256>>>();
    proj_mma      <<<dim3(2, 256, 2), 256>>>(pb, ls, out);
}

// round 11
// speedup vs baseline: 1.3739x; 1.0026x over previous
#include <cuda_runtime.h>
#include <cuda_bf16.h>
#include <cstdint>

// ---------------------------------------------------------------------------
// MobileAttention3D: B=2, C=256, D=32, H=W=32, NH=8, KD=VD=64
//
// R9 = R7 + truncation-split pack2 (LOP+FSUB+PRMT, 6 ops vs ~20) everywhere.
//   hi = trunc-bf16(x) via mask; lo = x - hi (exact); pair-pack via PRMT.
// bf16 2-term split, 3 MMAs per tile, fp32 accum => ~4e-5 rel err.
// ---------------------------------------------------------------------------

#define NPOS 32768

__device__ float    g_V  [2*32*65536];    // [b][j][e][sigma] (shuffled)
__device__ float    g_Ap [64*16*1024];    // partial logits [fc][bn][i*32+j]
__device__ float    g_A  [16*1024];       // softmaxed attn
__device__ uint32_t g_xph[2*128*32768];   // x bf16-hi pairs [b][cp][p]
__device__ uint32_t g_xpl[2*128*32768];
__device__ uint32_t g_oph[2*256*32768];   // proj-input hi pairs [b][ep][p']
__device__ uint32_t g_opl[2*256*32768];
__device__ uint32_t g_wqh[128*640];       // qkv W hi pairs [kp][oc]
__device__ uint32_t g_wql[128*640];
__device__ uint32_t g_wph[256*256];       // proj W hi pairs [kp][oc]
__device__ uint32_t g_wpl[256*256];
__device__ uint32_t g_Qh [2*8*32*32768];  // Q hi pairs [(bn*32+i)][fp]
__device__ uint32_t g_Ql [2*8*32*32768];
__device__ uint32_t g_Kh [2*32*32768];    // K hi pairs [(b*32+j)][fp]
__device__ uint32_t g_Kl [2*32*32768];

// ---- helpers ----
// Truncation split: hi = top-16 bits of fp32 (a valid bf16), lo = x - hi
// (exact in fp32), packed pairwise via PRMT. 6 ops total.
__device__ __forceinline__ void pack2(float a, float b, uint32_t& hi, uint32_t& lo) {
    const uint32_t au = __float_as_uint(a), bu = __float_as_uint(b);
    const float ah = __uint_as_float(au & 0xFFFF0000u);
    const float bh = __uint_as_float(bu & 0xFFFF0000u);
    hi = __byte_perm(au, bu, 0x7632);
    lo = __byte_perm(__float_as_uint(a - ah), __float_as_uint(b - bh), 0x7632);
}

__device__ __forceinline__ uint32_t smem_u32(const void* p) {
    uint32_t a;
    asm("{ .reg .u64 t; cvta.to.shared.u64 t, %1; cvt.u32.u64 %0, t; }" : "=r"(a) : "l"(p));
    return a;
}

#define MMA16816(d, a, bf) \
    asm volatile("mma.sync.aligned.m16n8k16.row.col.f32.bf16.bf16.f32 " \
        "{%0,%1,%2,%3}, {%4,%5,%6,%7}, {%8,%9}, {%0,%1,%2,%3};" \
        : "+f"((d)[0]), "+f"((d)[1]), "+f"((d)[2]), "+f"((d)[3]) \
        : "r"((a)[0]), "r"((a)[1]), "r"((a)[2]), "r"((a)[3]), \
          "r"((bf)[0]), "r"((bf)[1]))

#define CP16(dst, src) \
    asm volatile("cp.async.cg.shared.global [%0], [%1], 16;" :: "r"(dst), "l"(src) : "memory")
#define CP_COMMIT() asm volatile("cp.async.commit_group;" ::: "memory")
#define CP_WAIT0()  asm volatile("cp.async.wait_group 0;" ::: "memory")

#define ROWW 136
#define AOFF (8*ROWW*4)
#define BUFOFF (4*AOFF)

// ---------------------------------------------------------------------------
// K0a: convert x to packed bf16 hi/lo pairs over adjacent channels.
// ---------------------------------------------------------------------------
__global__ __launch_bounds__(256) void cvt_x(const float* __restrict__ x)
{
    const int p  = blockIdx.x * 1024 + threadIdx.x * 4;
    const int cp = blockIdx.y;
    const int b  = blockIdx.z;
    const float4 x0 = *(const float4*)&x[((size_t)(b * 256 + 2*cp    ) << 15) + p];
    const float4 x1 = *(const float4*)&x[((size_t)(b * 256 + 2*cp + 1) << 15) + p];
    uint4 h, l;
    pack2(x0.x, x1.x, h.x, l.x);
    pack2(x0.y, x1.y, h.y, l.y);
    pack2(x0.z, x1.z, h.z, l.z);
    pack2(x0.w, x1.w, h.w, l.w);
    const size_t o = ((size_t)(b * 128 + cp) << 15) + p;
    *(uint4*)&g_xph[o] = h;
    *(uint4*)&g_xpl[o] = l;
}

// ---------------------------------------------------------------------------
// K0b: pre-pack weights (k-pair-major).
// ---------------------------------------------------------------------------
__global__ __launch_bounds__(256) void pack_w(
    const float* __restrict__ qw, const float* __restrict__ kvw,
    const float* __restrict__ pw)
{
    const int id = blockIdx.x * 256 + threadIdx.x;
    if (id < 128 * 640) {
        const int kp = id / 640, oc = id % 640;
        const float* wr = (oc < 512) ? qw + (size_t)oc * 256
                                     : kvw + (size_t)(oc - 512) * 256;
        uint32_t h, l;
        pack2(wr[2*kp], wr[2*kp + 1], h, l);
        g_wqh[id] = h; g_wql[id] = l;
    } else {
        const int id2 = id - 128 * 640;
        if (id2 < 256 * 256) {
            const int kp = id2 >> 8, oc = id2 & 255;
            uint32_t h, l;
            pack2(pw[(size_t)oc * 512 + 2*kp], pw[(size_t)oc * 512 + 2*kp + 1], h, l);
            g_wph[id2] = h; g_wpl[id2] = l;
        }
    }
}

// ---------------------------------------------------------------------------
// qkv epilogue pair store: (oc, pos even) + (oc, pos+1).
// ---------------------------------------------------------------------------
__device__ __forceinline__ void store_pair(int b, int oc, int pos,
                                           float v0, float v1,
                                           const float* qb, const float* kvb)
{
    const int i = pos >> 10, s = pos & 1023, sp = s >> 1;
    if (oc < 512) {
        const float bias = qb[oc];
        uint32_t h, l;
        pack2(v0 + bias, v1 + bias, h, l);
        const size_t a = (size_t)((b*8 + (oc >> 6)) * 32 + i) * 32768 + (oc & 63) * 512 + sp;
        g_Qh[a] = h; g_Ql[a] = l;
    } else if (oc < 576) {
        const float bias = kvb[oc - 512];
        uint32_t h, l;
        pack2(v0 + bias, v1 + bias, h, l);
        const size_t a = (size_t)(b*32 + i) * 32768 + (oc - 512) * 512 + sp;
        g_Kh[a] = h; g_Kl[a] = l;
    } else {
        const float bias = kvb[oc - 512];
        const int cv = oc - 576;
        const int hh = s >> 5, w0 = s & 31;          // s even -> same h for s+1
        const int sigbase = ((hh >> 3) << 5) | ((hh & 7) << 2);
        const unsigned vb = ((unsigned)(b * 32 + i)) << 16;
        const int e20 = ((w0 & 7) << 6) | cv;
        const int e21 = (((w0 + 1) & 7) << 6) | cv;
        g_V[vb + (e20 << 7) + sigbase + (w0 >> 3)]       = v0 + bias;
        g_V[vb + (e21 << 7) + sigbase + ((w0 + 1) >> 3)] = v1 + bias;
    }
}

// ---------------------------------------------------------------------------
// Shared GEMM compute step (reads one smem buffer, 3-term split MMA).
// ---------------------------------------------------------------------------
__device__ __forceinline__ void gemm_step(
    const uint32_t* sm, int buf, int wm, int wn, int g, int t,
    float acc[4][4][4])
{
    const uint32_t* Awh = sm + (buf * 4 + 0) * 8 * ROWW;
    const uint32_t* Awl = sm + (buf * 4 + 1) * 8 * ROWW;
    const uint32_t* Bxh = sm + (buf * 4 + 2) * 8 * ROWW;
    const uint32_t* Bxl = sm + (buf * 4 + 3) * 8 * ROWW;

    uint32_t bh[4][2], bl[4][2];
#pragma unroll
    for (int nb = 0; nb < 4; nb++) {
        const int nbase = wn * 32 + nb * 8 + g;
        bh[nb][0] = Bxh[t * ROWW + nbase];       bh[nb][1] = Bxh[(t+4) * ROWW + nbase];
        bl[nb][0] = Bxl[t * ROWW + nbase];       bl[nb][1] = Bxl[(t+4) * ROWW + nbase];
    }
#pragma unroll
    for (int mb = 0; mb < 4; mb++) {
        const int mbase = wm * 64 + mb * 16 + g;
        uint32_t ah[4], al_[4];
        ah[0]  = Awh[t * ROWW + mbase];     ah[1]  = Awh[t * ROWW + mbase + 8];
        ah[2]  = Awh[(t+4) * ROWW + mbase]; ah[3]  = Awh[(t+4) * ROWW + mbase + 8];
        al_[0] = Awl[t * ROWW + mbase];     al_[1] = Awl[t * ROWW + mbase + 8];
        al_[2] = Awl[(t+4) * ROWW + mbase]; al_[3] = Awl[(t+4) * ROWW + mbase + 8];
#pragma unroll
        for (int nb = 0; nb < 4; nb++) {
            MMA16816(acc[mb][nb], ah,  bh[nb]);
            MMA16816(acc[mb][nb], ah,  bl[nb]);
            MMA16816(acc[mb][nb], al_, bh[nb]);
        }
    }
}

// ---------------------------------------------------------------------------
// K1: QKV GEMM. grid(5 mc, 256 p-tiles, 2 b).
// ---------------------------------------------------------------------------
__global__ __launch_bounds__(256) void qkv_mma(
    const float* __restrict__ qb, const float* __restrict__ kvb)
{
    __shared__ uint32_t sm[2 * 4 * 8 * ROWW];
    const int tid = threadIdx.x, lane = tid & 31, wid = tid >> 5;
    const int wm = wid & 1, wn = wid >> 1;
    const int g = lane >> 2, t = lane & 3;
    const int mc = blockIdx.x, p0 = blockIdx.y * 128, b = blockIdx.z;
    const uint32_t sbase = smem_u32(sm);

    const int r = tid >> 5, c4 = (tid & 31) * 4;
    const uint32_t dst0 = sbase + (r * ROWW + c4) * 4;

    float acc[4][4][4];
#pragma unroll
    for (int mb = 0; mb < 4; mb++)
#pragma unroll
        for (int nb = 0; nb < 4; nb++)
#pragma unroll
            for (int q = 0; q < 4; q++) acc[mb][nb][q] = 0.f;

    {
        const int wi = r * 640 + mc * 128 + c4;
        const size_t xi = ((size_t)(b * 128 + r) << 15) + p0 + c4;
        CP16(dst0,          &g_wqh[wi]);
        CP16(dst0 + AOFF,   &g_wql[wi]);
        CP16(dst0 + 2*AOFF, &g_xph[xi]);
        CP16(dst0 + 3*AOFF, &g_xpl[xi]);
        CP_COMMIT();
    }

    for (int s = 0; s < 16; s++) {
        CP_WAIT0();
        __syncthreads();
        if (s < 15) {
            const int sr = (s + 1) * 8 + r;
            const uint32_t d = dst0 + ((s + 1) & 1) * BUFOFF;
            const int wi = sr * 640 + mc * 128 + c4;
            const size_t xi = ((size_t)(b * 128 + sr) << 15) + p0 + c4;
            CP16(d,          &g_wqh[wi]);
            CP16(d + AOFF,   &g_wql[wi]);
            CP16(d + 2*AOFF, &g_xph[xi]);
            CP16(d + 3*AOFF, &g_xpl[xi]);
            CP_COMMIT();
        }
        gemm_step(sm, s & 1, wm, wn, g, t, acc);
    }

#pragma unroll
    for (int mb = 0; mb < 4; mb++) {
        const int oc_a = mc * 128 + wm * 64 + mb * 16 + g;
#pragma unroll
        for (int nb = 0; nb < 4; nb++) {
            const int pos_a = p0 + wn * 32 + nb * 8 + t * 2;
            store_pair(b, oc_a,     pos_a, acc[mb][nb][0], acc[mb][nb][1], qb, kvb);
            store_pair(b, oc_a + 8, pos_a, acc[mb][nb][2], acc[mb][nb][3], qb, kvb);
        }
    }
}

// ---------------------------------------------------------------------------
// K4: proj GEMM. grid(2 mc, 256 p-tiles, 2 b). K=512 -> 32 k-steps.
// ---------------------------------------------------------------------------
__global__ __launch_bounds__(256) void proj_mma(
    const float* __restrict__ pb, const float* __restrict__ ls,
    float* __restrict__ out)
{
    __shared__ uint32_t sm[2 * 4 * 8 * ROWW];
    const int tid = threadIdx.x, lane = tid & 31, wid = tid >> 5;
    const int wm = wid & 1, wn = wid >> 1;
    const int g = lane >> 2, t = lane & 3;
    const int mc = blockIdx.x, p0 = blockIdx.y * 128, b = blockIdx.z;
    const uint32_t sbase = smem_u32(sm);

    const int r = tid >> 5, c4 = (tid & 31) * 4;
    const uint32_t dst0 = sbase + (r * ROWW + c4) * 4;

    float acc[4][4][4];
#pragma unroll
    for (int mb = 0; mb < 4; mb++)
#pragma unroll
        for (int nb = 0; nb < 4; nb++)
#pragma unroll
            for (int q = 0; q < 4; q++) acc[mb][nb][q] = 0.f;

    {
        const int wi = r * 256 + mc * 128 + c4;
        const size_t xi = ((size_t)(b * 256 + r) << 15) + p0 + c4;
        CP16(dst0,          &g_wph[wi]);
        CP16(dst0 + AOFF,   &g_wpl[wi]);
        CP16(dst0 + 2*AOFF, &g_oph[xi]);
        CP16(dst0 + 3*AOFF, &g_opl[xi]);
        CP_COMMIT();
    }

    for (int s = 0; s < 32; s++) {
        CP_WAIT0();
        __syncthreads();
        if (s < 31) {
            const int sr = (s + 1) * 8 + r;
            const uint32_t d = dst0 + ((s + 1) & 1) * BUFOFF;
            const int wi = sr * 256 + mc * 128 + c4;
            const size_t xi = ((size_t)(b * 256 + sr) << 15) + p0 + c4;
            CP16(d,          &g_wph[wi]);
            CP16(d + AOFF,   &g_wpl[wi]);
            CP16(d + 2*AOFF, &g_oph[xi]);
            CP16(d + 3*AOFF, &g_opl[xi]);
            CP_COMMIT();
        }
        gemm_step(sm, s & 1, wm, wn, g, t, acc);
    }

#pragma unroll
    for (int mb = 0; mb < 4; mb++) {
        const int r0 = mc * 128 + wm * 64 + mb * 16 + g;
        const float b0 = pb[r0],     s0 = ls[r0];
        const float b1 = pb[r0 + 8], s1 = ls[r0 + 8];
#pragma unroll
        for (int nb = 0; nb < 4; nb++) {
            const int pos_a = p0 + wn * 32 + nb * 8 + t * 2;
            float* o0 = out + (((size_t)(b * 256 + r0)) << 15) + pos_a;
            float* o1 = out + (((size_t)(b * 256 + r0 + 8)) << 15) + pos_a;
            o0[0] = (acc[mb][nb][0] + b0) * s0;
            o0[1] = (acc[mb][nb][1] + b0) * s0;
            o1[0] = (acc[mb][nb][2] + b1) * s1;
            o1[1] = (acc[mb][nb][3] + b1) * s1;
        }
    }
}

// ---------------------------------------------------------------------------
// K2: scores via MMA. grid(64 fchunks, 16 bn), 128 thr (4 warps, f-split).
// ---------------------------------------------------------------------------
#define SROW 36
__global__ __launch_bounds__(128) void scores_mma()
{
    __shared__ uint32_t sm[2 * 4 * 32 * SROW];   // 36864 B
    const int tid = threadIdx.x, lane = tid & 31, w = tid >> 5;
    const int g = lane >> 2, t = lane & 3;
    const int fc = blockIdx.x, bn = blockIdx.y, b = bn >> 3;
    const uint32_t sbase = smem_u32(sm);

    const int r = tid >> 2, q = tid & 3;
    const size_t qrow = ((size_t)(bn * 32 + r)) * 32768 + fc * 512 + q * 8;
    const size_t krow = ((size_t)(b  * 32 + r)) * 32768 + fc * 512 + q * 8;
    const uint32_t dst0 = sbase + (r * SROW + q * 8) * 4;
    const uint32_t A1 = 32 * SROW * 4;

    float acc[2][4][4];
#pragma unroll
    for (int mi = 0; mi < 2; mi++)
#pragma unroll
        for (int ni = 0; ni < 4; ni++)
#pragma unroll
            for (int z = 0; z < 4; z++) acc[mi][ni][z] = 0.f;

    {
        CP16(dst0,        &g_Qh[qrow]);     CP16(dst0 + 16,        &g_Qh[qrow + 4]);
        CP16(dst0 + A1,   &g_Ql[qrow]);     CP16(dst0 + A1 + 16,   &g_Ql[qrow + 4]);
        CP16(dst0 + 2*A1, &g_Kh[krow]);     CP16(dst0 + 2*A1 + 16, &g_Kh[krow + 4]);
        CP16(dst0 + 3*A1, &g_Kl[krow]);     CP16(dst0 + 3*A1 + 16, &g_Kl[krow + 4]);
        CP_COMMIT();
    }

    for (int tl = 0; tl < 16; tl++) {
        CP_WAIT0();
        __syncthreads();
        if (tl < 15) {
            const uint32_t d = dst0 + ((tl + 1) & 1) * (4 * A1);
            const size_t qo = qrow + (tl + 1) * 32, ko = krow + (tl + 1) * 32;
            CP16(d,        &g_Qh[qo]);     CP16(d + 16,        &g_Qh[qo + 4]);
            CP16(d + A1,   &g_Ql[qo]);     CP16(d + A1 + 16,   &g_Ql[qo + 4]);
            CP16(d + 2*A1, &g_Kh[ko]);     CP16(d + 2*A1 + 16, &g_Kh[ko + 4]);
            CP16(d + 3*A1, &g_Kl[ko]);     CP16(d + 3*A1 + 16, &g_Kl[ko + 4]);
            CP_COMMIT();
        }
        const uint32_t* Qh = sm + ((tl & 1) * 4 + 0) * 32 * SROW;
        const uint32_t* Ql = sm + ((tl & 1) * 4 + 1) * 32 * SROW;
        const uint32_t* Kh = sm + ((tl & 1) * 4 + 2) * 32 * SROW;
        const uint32_t* Kl = sm + ((tl & 1) * 4 + 3) * 32 * SROW;
        const int kp = w * 8;

        uint32_t bh[4][2], bl[4][2];
#pragma unroll
        for (int ni = 0; ni < 4; ni++) {
            const int col = ni * 8 + g;
            bh[ni][0] = Kh[col * SROW + kp + t];
            bh[ni][1] = Kh[col * SROW + kp + t + 4];
            bl[ni][0] = Kl[col * SROW + kp + t];
            bl[ni][1] = Kl[col * SROW + kp + t + 4];
        }
#pragma unroll
        for (int mi = 0; mi < 2; mi++) {
            const int row = mi * 16 + g;
            uint32_t ah[4], al_[4];
            ah[0]  = Qh[row * SROW + kp + t];       ah[1]  = Qh[(row + 8) * SROW + kp + t];
            ah[2]  = Qh[row * SROW + kp + t + 4];   ah[3]  = Qh[(row + 8) * SROW + kp + t + 4];
            al_[0] = Ql[row * SROW + kp + t];       al_[1] = Ql[(row + 8) * SROW + kp + t];
            al_[2] = Ql[row * SROW + kp + t + 4];   al_[3] = Ql[(row + 8) * SROW + kp + t + 4];
#pragma unroll
            for (int ni = 0; ni < 4; ni++) {
                MMA16816(acc[mi][ni], ah,  bh[ni]);
                MMA16816(acc[mi][ni], ah,  bl[ni]);
                MMA16816(acc[mi][ni], al_, bh[ni]);
            }
        }
    }

    __syncthreads();
    float* red = (float*)sm;
#pragma unroll
    for (int mi = 0; mi < 2; mi++)
#pragma unroll
        for (int ni = 0; ni < 4; ni++) {
            const int i0 = mi * 16 + g, j0 = ni * 8 + t * 2;
            red[w * 1024 + i0 * 32 + j0]           = acc[mi][ni][0];
            red[w * 1024 + i0 * 32 + j0 + 1]       = acc[mi][ni][1];
            red[w * 1024 + (i0 + 8) * 32 + j0]     = acc[mi][ni][2];
            red[w * 1024 + (i0 + 8) * 32 + j0 + 1] = acc[mi][ni][3];
        }
    __syncthreads();
    const unsigned abase = (unsigned)(fc * 16 + bn) * 1024u;
#pragma unroll
    for (int e = 0; e < 8; e++) {
        const int idx = tid * 8 + e;
        g_Ap[abase + idx] = red[idx] + red[1024 + idx] + red[2048 + idx] + red[3072 + idx];
    }
}

// ---------------------------------------------------------------------------
__global__ __launch_bounds__(1024) void softmax_kernel()
{
    const int bn = blockIdx.x;
    const int tid = threadIdx.x;
    const int i = tid >> 5, j = tid & 31;
    float v = 0.f;
#pragma unroll
    for (int c = 0; c < 64; c++)
        v += g_Ap[((unsigned)(c * 16 + bn) << 10) + (i << 5) + j];
    v *= 0.125f;
    float m = v;
#pragma unroll
    for (int o = 16; o; o >>= 1) m = fmaxf(m, __shfl_xor_sync(0xffffffffu, m, o));
    float e = expf(v - m);
    float s = e;
#pragma unroll
    for (int o = 16; o; o >>= 1) s += __shfl_xor_sync(0xffffffffu, s, o);
    g_A[((unsigned)bn << 10) + (i << 5) + j] = e / s;
}

// ---------------------------------------------------------------------------
// K3: O' = A @ V'. Writes proj input as packed bf16 hi/lo pairs (coalesced).
// ---------------------------------------------------------------------------
__global__ __launch_bounds__(256) void av_kernel()
{
    __shared__ __align__(16) float As[1024];
    __shared__ float Vs[2][32][128];
    const int tid = threadIdx.x;
    const int bn = blockIdx.y;
    const int b = bn >> 3, n = bn & 7;
    const int e0 = blockIdx.x * 16;

#pragma unroll
    for (int l = 0; l < 4; l++)
        As[l * 256 + tid] = g_A[((unsigned)bn << 10) + l * 256 + tid];
    __syncthreads();

    const int eh  = tid >> 7;
    const int sig = tid & 127;
    const unsigned vbase = ((unsigned)(b * 32)) << 16;

    for (int ei = 0; ei < 16; ei += 2) {
        const int e = e0 + ei + eh;
#pragma unroll
        for (int j = 0; j < 32; j++)
            Vs[eh][j][sig] = g_V[vbase + ((unsigned)j << 16) + (e << 7) + sig];
        __syncthreads();

        float v[32];
#pragma unroll
        for (int j = 0; j < 32; j++) v[j] = Vs[eh][j][sig];

        float acc[32];
#pragma unroll
        for (int i = 0; i < 32; i++) acc[i] = 0.f;
#pragma unroll
        for (int i = 0; i < 32; i++) {
#pragma unroll
            for (int j4 = 0; j4 < 8; j4++) {
                const float4 a = *(const float4*)&As[(i << 5) + j4 * 4];
                acc[i] += a.x * v[j4*4] + a.y * v[j4*4+1] + a.z * v[j4*4+2] + a.w * v[j4*4+3];
            }
        }
        __syncthreads();
#pragma unroll
        for (int i = 0; i < 32; i++) Vs[eh][i][sig] = acc[i];
        __syncthreads();

        const int ep = (e0 + ei) >> 1;
        const size_t obase = ((size_t)(b * 256 + ep) << 15) + (n << 7) + sig;
#pragma unroll
        for (int ii = 0; ii < 16; ii++) {
            const int i = eh * 16 + ii;
            uint32_t h, l;
            pack2(Vs[0][i][sig], Vs[1][i][sig], h, l);
            g_oph[obase + ((size_t)i << 10)] = h;
            g_opl[obase + ((size_t)i << 10)] = l;
        }
        __syncthreads();
    }
}

// ---------------------------------------------------------------------------
extern "C" void kernel_launch(void* const* d_in, const int* in_sizes, int n_in,
                              void* d_out, int out_size)
{
    (void)in_sizes; (void)n_in; (void)out_size;
    const float* x   = (const float*)d_in[0];
    const float* qw  = (const float*)d_in[1];
    const float* qb  = (const float*)d_in[2];
    const float* kvb_dummy = nullptr; (void)kvb_dummy;
    const float* kvw = (const float*)d_in[3];
    const float* kvb = (const float*)d_in[4];
    const float* pw  = (const float*)d_in[5];
    const float* pb  = (const float*)d_in[6];
    const float* ls  = (const float*)d_in[7];
    float* out = (float*)d_out;

    pack_w        <<<576, 256>>>(qw, kvw, pw);
    cvt_x         <<<dim3(32, 128, 2), 256>>>(x);
    qkv_mma       <<<dim3(5, 256, 2), 256>>>(qb, kvb);
    scores_mma    <<<dim3(64, 16), 128>>>();
    softmax_kernel<<<16, 1024>>>();
    av_kernel     <<<dim3(32, 16), 256>>>();
    proj_mma      <<<dim3(2, 256, 2), 256>>>(pb, ls, out);
}

// round 13
// speedup vs baseline: 1.3769x; 1.0022x over previous
#include <cuda_runtime.h>
#include <cuda_bf16.h>
#include <cstdint>

// ---------------------------------------------------------------------------
// MobileAttention3D: B=2, C=256, D=32, H=W=32, NH=8, KD=VD=64
//
// R12 = R11 + latency-hiding fixes:
//   - av_kernel: acc split 32->16, __launch_bounds__(256,2) => 2 CTA/SM
//   - qkv/proj: triple-buffered cp.async (wait_group 1), dynamic smem 52KB
// bf16 2-term truncation split, 3 MMAs per tile, fp32 accum.
// ---------------------------------------------------------------------------

#define NPOS 32768

__device__ float    g_V  [2*32*65536];    // [b][j][e][sigma] (shuffled)
__device__ float    g_Ap [64*16*1024];    // partial logits [fc][bn][i*32+j]
__device__ float    g_A  [16*1024];       // softmaxed attn
__device__ uint32_t g_xph[2*128*32768];   // x bf16-hi pairs [b][cp][p]
__device__ uint32_t g_xpl[2*128*32768];
__device__ uint32_t g_oph[2*256*32768];   // proj-input hi pairs [b][ep][p']
__device__ uint32_t g_opl[2*256*32768];
__device__ uint32_t g_wqh[128*640];       // qkv W hi pairs [kp][oc]
__device__ uint32_t g_wql[128*640];
__device__ uint32_t g_wph[256*256];       // proj W hi pairs [kp][oc]
__device__ uint32_t g_wpl[256*256];
__device__ uint32_t g_Qh [2*8*32*32768];  // Q hi pairs [(bn*32+i)][fp]
__device__ uint32_t g_Ql [2*8*32*32768];
__device__ uint32_t g_Kh [2*32*32768];    // K hi pairs [(b*32+j)][fp]
__device__ uint32_t g_Kl [2*32*32768];

// ---- helpers ----
// Truncation split: hi = top-16 bits of fp32 (valid bf16), lo = x - hi (exact),
// pair-packed via PRMT.
__device__ __forceinline__ void pack2(float a, float b, uint32_t& hi, uint32_t& lo) {
    const uint32_t au = __float_as_uint(a), bu = __float_as_uint(b);
    const float ah = __uint_as_float(au & 0xFFFF0000u);
    const float bh = __uint_as_float(bu & 0xFFFF0000u);
    hi = __byte_perm(au, bu, 0x7632);
    lo = __byte_perm(__float_as_uint(a - ah), __float_as_uint(b - bh), 0x7632);
}

__device__ __forceinline__ uint32_t smem_u32(const void* p) {
    uint32_t a;
    asm("{ .reg .u64 t; cvta.to.shared.u64 t, %1; cvt.u32.u64 %0, t; }" : "=r"(a) : "l"(p));
    return a;
}

#define MMA16816(d, a, bf) \
    asm volatile("mma.sync.aligned.m16n8k16.row.col.f32.bf16.bf16.f32 " \
        "{%0,%1,%2,%3}, {%4,%5,%6,%7}, {%8,%9}, {%0,%1,%2,%3};" \
        : "+f"((d)[0]), "+f"((d)[1]), "+f"((d)[2]), "+f"((d)[3]) \
        : "r"((a)[0]), "r"((a)[1]), "r"((a)[2]), "r"((a)[3]), \
          "r"((bf)[0]), "r"((bf)[1]))

#define CP16(dst, src) \
    asm volatile("cp.async.cg.shared.global [%0], [%1], 16;" :: "r"(dst), "l"(src) : "memory")
#define CP_COMMIT() asm volatile("cp.async.commit_group;" ::: "memory")
#define CP_WAIT0()  asm volatile("cp.async.wait_group 0;" ::: "memory")
#define CP_WAIT1()  asm volatile("cp.async.wait_group 1;" ::: "memory")

#define ROWW 136
#define AOFF (8*ROWW*4)             // bytes per array within a buffer
#define QBUFB (4*AOFF)              // bytes per buffer (4 arrays)
#define SMEM_3BUF (3*QBUFB)         // 52224 bytes

// ---------------------------------------------------------------------------
// K0a: convert x to packed bf16 hi/lo pairs over adjacent channels.
// ---------------------------------------------------------------------------
__global__ __launch_bounds__(256) void cvt_x(const float* __restrict__ x)
{
    const int p  = blockIdx.x * 1024 + threadIdx.x * 4;
    const int cp = blockIdx.y;
    const int b  = blockIdx.z;
    const float4 x0 = *(const float4*)&x[((size_t)(b * 256 + 2*cp    ) << 15) + p];
    const float4 x1 = *(const float4*)&x[((size_t)(b * 256 + 2*cp + 1) << 15) + p];
    uint4 h, l;
    pack2(x0.x, x1.x, h.x, l.x);
    pack2(x0.y, x1.y, h.y, l.y);
    pack2(x0.z, x1.z, h.z, l.z);
    pack2(x0.w, x1.w, h.w, l.w);
    const size_t o = ((size_t)(b * 128 + cp) << 15) + p;
    *(uint4*)&g_xph[o] = h;
    *(uint4*)&g_xpl[o] = l;
}

// ---------------------------------------------------------------------------
// K0b: pre-pack weights (k-pair-major).
// ---------------------------------------------------------------------------
__global__ __launch_bounds__(256) void pack_w(
    const float* __restrict__ qw, const float* __restrict__ kvw,
    const float* __restrict__ pw)
{
    const int id = blockIdx.x * 256 + threadIdx.x;
    if (id < 128 * 640) {
        const int kp = id / 640, oc = id % 640;
        const float* wr = (oc < 512) ? qw + (size_t)oc * 256
                                     : kvw + (size_t)(oc - 512) * 256;
        uint32_t h, l;
        pack2(wr[2*kp], wr[2*kp + 1], h, l);
        g_wqh[id] = h; g_wql[id] = l;
    } else {
        const int id2 = id - 128 * 640;
        if (id2 < 256 * 256) {
            const int kp = id2 >> 8, oc = id2 & 255;
            uint32_t h, l;
            pack2(pw[(size_t)oc * 512 + 2*kp], pw[(size_t)oc * 512 + 2*kp + 1], h, l);
            g_wph[id2] = h; g_wpl[id2] = l;
        }
    }
}

// ---------------------------------------------------------------------------
// qkv epilogue pair store: (oc, pos even) + (oc, pos+1).
// ---------------------------------------------------------------------------
__device__ __forceinline__ void store_pair(int b, int oc, int pos,
                                           float v0, float v1,
                                           const float* qb, const float* kvb)
{
    const int i = pos >> 10, s = pos & 1023, sp = s >> 1;
    if (oc < 512) {
        const float bias = qb[oc];
        uint32_t h, l;
        pack2(v0 + bias, v1 + bias, h, l);
        const size_t a = (size_t)((b*8 + (oc >> 6)) * 32 + i) * 32768 + (oc & 63) * 512 + sp;
        g_Qh[a] = h; g_Ql[a] = l;
    } else if (oc < 576) {
        const float bias = kvb[oc - 512];
        uint32_t h, l;
        pack2(v0 + bias, v1 + bias, h, l);
        const size_t a = (size_t)(b*32 + i) * 32768 + (oc - 512) * 512 + sp;
        g_Kh[a] = h; g_Kl[a] = l;
    } else {
        const float bias = kvb[oc - 512];
        const int cv = oc - 576;
        const int hh = s >> 5, w0 = s & 31;          // s even -> same h for s+1
        const int sigbase = ((hh >> 3) << 5) | ((hh & 7) << 2);
        const unsigned vb = ((unsigned)(b * 32 + i)) << 16;
        const int e20 = ((w0 & 7) << 6) | cv;
        const int e21 = (((w0 + 1) & 7) << 6) | cv;
        g_V[vb + (e20 << 7) + sigbase + (w0 >> 3)]       = v0 + bias;
        g_V[vb + (e21 << 7) + sigbase + ((w0 + 1) >> 3)] = v1 + bias;
    }
}

// ---------------------------------------------------------------------------
// Shared GEMM compute step (reads one smem buffer, 3-term split MMA).
// ---------------------------------------------------------------------------
__device__ __forceinline__ void gemm_step(
    const uint32_t* sm, int buf, int wm, int wn, int g, int t,
    float acc[4][4][4])
{
    const uint32_t* Awh = sm + (buf * 4 + 0) * 8 * ROWW;
    const uint32_t* Awl = sm + (buf * 4 + 1) * 8 * ROWW;
    const uint32_t* Bxh = sm + (buf * 4 + 2) * 8 * ROWW;
    const uint32_t* Bxl = sm + (buf * 4 + 3) * 8 * ROWW;

    uint32_t bh[4][2], bl[4][2];
#pragma unroll
    for (int nb = 0; nb < 4; nb++) {
        const int nbase = wn * 32 + nb * 8 + g;
        bh[nb][0] = Bxh[t * ROWW + nbase];       bh[nb][1] = Bxh[(t+4) * ROWW + nbase];
        bl[nb][0] = Bxl[t * ROWW + nbase];       bl[nb][1] = Bxl[(t+4) * ROWW + nbase];
    }
#pragma unroll
    for (int mb = 0; mb < 4; mb++) {
        const int mbase = wm * 64 + mb * 16 + g;
        uint32_t ah[4], al_[4];
        ah[0]  = Awh[t * ROWW + mbase];     ah[1]  = Awh[t * ROWW + mbase + 8];
        ah[2]  = Awh[(t+4) * ROWW + mbase]; ah[3]  = Awh[(t+4) * ROWW + mbase + 8];
        al_[0] = Awl[t * ROWW + mbase];     al_[1] = Awl[t * ROWW + mbase + 8];
        al_[2] = Awl[(t+4) * ROWW + mbase]; al_[3] = Awl[(t+4) * ROWW + mbase + 8];
#pragma unroll
        for (int nb = 0; nb < 4; nb++) {
            MMA16816(acc[mb][nb], ah,  bh[nb]);
            MMA16816(acc[mb][nb], ah,  bl[nb]);
            MMA16816(acc[mb][nb], al_, bh[nb]);
        }
    }
}

// ---------------------------------------------------------------------------
// K1: QKV GEMM. grid(5 mc, 256 p-tiles, 2 b). Triple-buffered cp.async.
// ---------------------------------------------------------------------------
__global__ __launch_bounds__(256) void qkv_mma(
    const float* __restrict__ qb, const float* __restrict__ kvb)
{
    extern __shared__ uint32_t dsm[];
    const int tid = threadIdx.x, lane = tid & 31, wid = tid >> 5;
    const int wm = wid & 1, wn = wid >> 1;
    const int g = lane >> 2, t = lane & 3;
    const int mc = blockIdx.x, p0 = blockIdx.y * 128, b = blockIdx.z;
    const uint32_t sbase = smem_u32(dsm);

    const int r = tid >> 5, c4 = (tid & 31) * 4;
    const uint32_t dst0 = sbase + (r * ROWW + c4) * 4;

#define QKV_PF(s, d) { \
    const int sr_ = (s) * 8 + r; \
    const int wi_ = sr_ * 640 + mc * 128 + c4; \
    const size_t xi_ = ((size_t)(b * 128 + sr_) << 15) + p0 + c4; \
    CP16((d),          &g_wqh[wi_]); \
    CP16((d) + AOFF,   &g_wql[wi_]); \
    CP16((d) + 2*AOFF, &g_xph[xi_]); \
    CP16((d) + 3*AOFF, &g_xpl[xi_]); \
    CP_COMMIT(); }

    float acc[4][4][4];
#pragma unroll
    for (int mb = 0; mb < 4; mb++)
#pragma unroll
        for (int nb = 0; nb < 4; nb++)
#pragma unroll
            for (int q = 0; q < 4; q++) acc[mb][nb][q] = 0.f;

    QKV_PF(0, dst0);
    QKV_PF(1, dst0 + QBUFB);

    for (int s = 0; s < 16; s++) {
        CP_WAIT1();
        __syncthreads();
        if (s + 2 < 16) {
            QKV_PF(s + 2, dst0 + ((s + 2) % 3) * QBUFB);
        } else {
            CP_COMMIT();     // empty group keeps wait_group accounting correct
        }
        gemm_step(dsm, s % 3, wm, wn, g, t, acc);
    }

#pragma unroll
    for (int mb = 0; mb < 4; mb++) {
        const int oc_a = mc * 128 + wm * 64 + mb * 16 + g;
#pragma unroll
        for (int nb = 0; nb < 4; nb++) {
            const int pos_a = p0 + wn * 32 + nb * 8 + t * 2;
            store_pair(b, oc_a,     pos_a, acc[mb][nb][0], acc[mb][nb][1], qb, kvb);
            store_pair(b, oc_a + 8, pos_a, acc[mb][nb][2], acc[mb][nb][3], qb, kvb);
        }
    }
#undef QKV_PF
}

// ---------------------------------------------------------------------------
// K4: proj GEMM. grid(2 mc, 256 p-tiles, 2 b). Triple-buffered, 32 k-steps.
// ---------------------------------------------------------------------------
__global__ __launch_bounds__(256) void proj_mma(
    const float* __restrict__ pb, const float* __restrict__ ls,
    float* __restrict__ out)
{
    extern __shared__ uint32_t dsm[];
    const int tid = threadIdx.x, lane = tid & 31, wid = tid >> 5;
    const int wm = wid & 1, wn = wid >> 1;
    const int g = lane >> 2, t = lane & 3;
    const int mc = blockIdx.x, p0 = blockIdx.y * 128, b = blockIdx.z;
    const uint32_t sbase = smem_u32(dsm);

    const int r = tid >> 5, c4 = (tid & 31) * 4;
    const uint32_t dst0 = sbase + (r * ROWW + c4) * 4;

#define PROJ_PF(s, d) { \
    const int sr_ = (s) * 8 + r; \
    const int wi_ = sr_ * 256 + mc * 128 + c4; \
    const size_t xi_ = ((size_t)(b * 256 + sr_) << 15) + p0 + c4; \
    CP16((d),          &g_wph[wi_]); \
    CP16((d) + AOFF,   &g_wpl[wi_]); \
    CP16((d) + 2*AOFF, &g_oph[xi_]); \
    CP16((d) + 3*AOFF, &g_opl[xi_]); \
    CP_COMMIT(); }

    float acc[4][4][4];
#pragma unroll
    for (int mb = 0; mb < 4; mb++)
#pragma unroll
        for (int nb = 0; nb < 4; nb++)
#pragma unroll
            for (int q = 0; q < 4; q++) acc[mb][nb][q] = 0.f;

    PROJ_PF(0, dst0);
    PROJ_PF(1, dst0 + QBUFB);

    for (int s = 0; s < 32; s++) {
        CP_WAIT1();
        __syncthreads();
        if (s + 2 < 32) {
            PROJ_PF(s + 2, dst0 + ((s + 2) % 3) * QBUFB);
        } else {
            CP_COMMIT();
        }
        gemm_step(dsm, s % 3, wm, wn, g, t, acc);
    }

#pragma unroll
    for (int mb = 0; mb < 4; mb++) {
        const int r0 = mc * 128 + wm * 64 + mb * 16 + g;
        const float b0 = pb[r0],     s0 = ls[r0];
        const float b1 = pb[r0 + 8], s1 = ls[r0 + 8];
#pragma unroll
        for (int nb = 0; nb < 4; nb++) {
            const int pos_a = p0 + wn * 32 + nb * 8 + t * 2;
            float* o0 = out + (((size_t)(b * 256 + r0)) << 15) + pos_a;
            float* o1 = out + (((size_t)(b * 256 + r0 + 8)) << 15) + pos_a;
            o0[0] = (acc[mb][nb][0] + b0) * s0;
            o0[1] = (acc[mb][nb][1] + b0) * s0;
            o1[0] = (acc[mb][nb][2] + b1) * s1;
            o1[1] = (acc[mb][nb][3] + b1) * s1;
        }
    }
#undef PROJ_PF
}

// ---------------------------------------------------------------------------
// K2: scores via MMA. grid(64 fchunks, 16 bn), 128 thr (4 warps, f-split).
// ---------------------------------------------------------------------------
#define SROW 36
__global__ __launch_bounds__(128) void scores_mma()
{
    __shared__ uint32_t sm[2 * 4 * 32 * SROW];   // 36864 B
    const int tid = threadIdx.x, lane = tid & 31, w = tid >> 5;
    const int g = lane >> 2, t = lane & 3;
    const int fc = blockIdx.x, bn = blockIdx.y, b = bn >> 3;
    const uint32_t sbase = smem_u32(sm);

    const int r = tid >> 2, q = tid & 3;
    const size_t qrow = ((size_t)(bn * 32 + r)) * 32768 + fc * 512 + q * 8;
    const size_t krow = ((size_t)(b  * 32 + r)) * 32768 + fc * 512 + q * 8;
    const uint32_t dst0 = sbase + (r * SROW + q * 8) * 4;
    const uint32_t A1 = 32 * SROW * 4;

    float acc[2][4][4];
#pragma unroll
    for (int mi = 0; mi < 2; mi++)
#pragma unroll
        for (int ni = 0; ni < 4; ni++)
#pragma unroll
            for (int z = 0; z < 4; z++) acc[mi][ni][z] = 0.f;

    {
        CP16(dst0,        &g_Qh[qrow]);     CP16(dst0 + 16,        &g_Qh[qrow + 4]);
        CP16(dst0 + A1,   &g_Ql[qrow]);     CP16(dst0 + A1 + 16,   &g_Ql[qrow + 4]);
        CP16(dst0 + 2*A1, &g_Kh[krow]);     CP16(dst0 + 2*A1 + 16, &g_Kh[krow + 4]);
        CP16(dst0 + 3*A1, &g_Kl[krow]);     CP16(dst0 + 3*A1 + 16, &g_Kl[krow + 4]);
        CP_COMMIT();
    }

    for (int tl = 0; tl < 16; tl++) {
        CP_WAIT0();
        __syncthreads();
        if (tl < 15) {
            const uint32_t d = dst0 + ((tl + 1) & 1) * (4 * A1);
            const size_t qo = qrow + (tl + 1) * 32, ko = krow + (tl + 1) * 32;
            CP16(d,        &g_Qh[qo]);     CP16(d + 16,        &g_Qh[qo + 4]);
            CP16(d + A1,   &g_Ql[qo]);     CP16(d + A1 + 16,   &g_Ql[qo + 4]);
            CP16(d + 2*A1, &g_Kh[ko]);     CP16(d + 2*A1 + 16, &g_Kh[ko + 4]);
            CP16(d + 3*A1, &g_Kl[ko]);     CP16(d + 3*A1 + 16, &g_Kl[ko + 4]);
            CP_COMMIT();
        }
        const uint32_t* Qh = sm + ((tl & 1) * 4 + 0) * 32 * SROW;
        const uint32_t* Ql = sm + ((tl & 1) * 4 + 1) * 32 * SROW;
        const uint32_t* Kh = sm + ((tl & 1) * 4 + 2) * 32 * SROW;
        const uint32_t* Kl = sm + ((tl & 1) * 4 + 3) * 32 * SROW;
        const int kp = w * 8;

        uint32_t bh[4][2], bl[4][2];
#pragma unroll
        for (int ni = 0; ni < 4; ni++) {
            const int col = ni * 8 + g;
            bh[ni][0] = Kh[col * SROW + kp + t];
            bh[ni][1] = Kh[col * SROW + kp + t + 4];
            bl[ni][0] = Kl[col * SROW + kp + t];
            bl[ni][1] = Kl[col * SROW + kp + t + 4];
        }
#pragma unroll
        for (int mi = 0; mi < 2; mi++) {
            const int row = mi * 16 + g;
            uint32_t ah[4], al_[4];
            ah[0]  = Qh[row * SROW + kp + t];       ah[1]  = Qh[(row + 8) * SROW + kp + t];
            ah[2]  = Qh[row * SROW + kp + t + 4];   ah[3]  = Qh[(row + 8) * SROW + kp + t + 4];
            al_[0] = Ql[row * SROW + kp + t];       al_[1] = Ql[(row + 8) * SROW + kp + t];
            al_[2] = Ql[row * SROW + kp + t + 4];   al_[3] = Ql[(row + 8) * SROW + kp + t + 4];
#pragma unroll
            for (int ni = 0; ni < 4; ni++) {
                MMA16816(acc[mi][ni], ah,  bh[ni]);
                MMA16816(acc[mi][ni], ah,  bl[ni]);
                MMA16816(acc[mi][ni], al_, bh[ni]);
            }
        }
    }

    __syncthreads();
    float* red = (float*)sm;
#pragma unroll
    for (int mi = 0; mi < 2; mi++)
#pragma unroll
        for (int ni = 0; ni < 4; ni++) {
            const int i0 = mi * 16 + g, j0 = ni * 8 + t * 2;
            red[w * 1024 + i0 * 32 + j0]           = acc[mi][ni][0];
            red[w * 1024 + i0 * 32 + j0 + 1]       = acc[mi][ni][1];
            red[w * 1024 + (i0 + 8) * 32 + j0]     = acc[mi][ni][2];
            red[w * 1024 + (i0 + 8) * 32 + j0 + 1] = acc[mi][ni][3];
        }
    __syncthreads();
    const unsigned abase = (unsigned)(fc * 16 + bn) * 1024u;
#pragma unroll
    for (int e = 0; e < 8; e++) {
        const int idx = tid * 8 + e;
        g_Ap[abase + idx] = red[idx] + red[1024 + idx] + red[2048 + idx] + red[3072 + idx];
    }
}

// ---------------------------------------------------------------------------
__global__ __launch_bounds__(1024) void softmax_kernel()
{
    const int bn = blockIdx.x;
    const int tid = threadIdx.x;
    const int i = tid >> 5, j = tid & 31;
    float v = 0.f;
#pragma unroll
    for (int c = 0; c < 64; c++)
        v += g_Ap[((unsigned)(c * 16 + bn) << 10) + (i << 5) + j];
    v *= 0.125f;
    float m = v;
#pragma unroll
    for (int o = 16; o; o >>= 1) m = fmaxf(m, __shfl_xor_sync(0xffffffffu, m, o));
    float e = expf(v - m);
    float s = e;
#pragma unroll
    for (int o = 16; o; o >>= 1) s += __shfl_xor_sync(0xffffffffu, s, o);
    g_A[((unsigned)bn << 10) + (i << 5) + j] = e / s;
}

// ---------------------------------------------------------------------------
// K3: O' = A @ V'. acc split into two halves of 16 => ~75 regs => 2 CTA/SM.
// ---------------------------------------------------------------------------
__global__ __launch_bounds__(256, 2) void av_kernel()
{
    __shared__ __align__(16) float As[1024];
    __shared__ float Vs[2][32][128];
    const int tid = threadIdx.x;
    const int bn = blockIdx.y;
    const int b = bn >> 3, n = bn & 7;
    const int e0 = blockIdx.x * 16;

#pragma unroll
    for (int l = 0; l < 4; l++)
        As[l * 256 + tid] = g_A[((unsigned)bn << 10) + l * 256 + tid];
    __syncthreads();

    const int eh  = tid >> 7;
    const int sig = tid & 127;
    const unsigned vbase = ((unsigned)(b * 32)) << 16;

    for (int ei = 0; ei < 16; ei += 2) {
        const int e = e0 + ei + eh;
#pragma unroll
        for (int j = 0; j < 32; j++)
            Vs[eh][j][sig] = g_V[vbase + ((unsigned)j << 16) + (e << 7) + sig];
        __syncthreads();

        float v[32];
#pragma unroll
        for (int j = 0; j < 32; j++) v[j] = Vs[eh][j][sig];

        // Vs[eh][*][sig] is only read by this thread -> safe to overwrite
        // after copying to registers, no sync needed.
#pragma unroll
        for (int half = 0; half < 2; half++) {
            float acc[16];
#pragma unroll
            for (int i = 0; i < 16; i++) acc[i] = 0.f;
#pragma unroll
            for (int i = 0; i < 16; i++) {
                const int ig = half * 16 + i;
#pragma unroll
                for (int j4 = 0; j4 < 8; j4++) {
                    const float4 a = *(const float4*)&As[(ig << 5) + j4 * 4];
                    acc[i] += a.x * v[j4*4] + a.y * v[j4*4+1]
                            + a.z * v[j4*4+2] + a.w * v[j4*4+3];
                }
            }
#pragma unroll
            for (int i = 0; i < 16; i++)
                Vs[eh][half * 16 + i][sig] = acc[i];
        }
        __syncthreads();

        const int ep = (e0 + ei) >> 1;
        const size_t obase = ((size_t)(b * 256 + ep) << 15) + (n << 7) + sig;
#pragma unroll
        for (int ii = 0; ii < 16; ii++) {
            const int i = eh * 16 + ii;
            uint32_t h, l;
            pack2(Vs[0][i][sig], Vs[1][i][sig], h, l);
            g_oph[obase + ((size_t)i << 10)] = h;
            g_opl[obase + ((size_t)i << 10)] = l;
        }
        __syncthreads();
    }
}

// ---------------------------------------------------------------------------
extern "C" void kernel_launch(void* const* d_in, const int* in_sizes, int n_in,
                              void* d_out, int out_size)
{
    (void)in_sizes; (void)n_in; (void)out_size;
    const float* x   = (const float*)d_in[0];
    const float* qw  = (const float*)d_in[1];
    const float* qb  = (const float*)d_in[2];
    const float* kvw = (const float*)d_in[3];
    const float* kvb = (const float*)d_in[4];
    const float* pw  = (const float*)d_in[5];
    const float* pb  = (const float*)d_in[6];
    const float* ls  = (const float*)d_in[7];
    float* out = (float*)d_out;

    static bool attr_set = false;
    if (!attr_set) {
        cudaFuncSetAttribute((const void*)qkv_mma,
                             cudaFuncAttributeMaxDynamicSharedMemorySize, SMEM_3BUF);
        cudaFuncSetAttribute((const void*)proj_mma,
                             cudaFuncAttributeMaxDynamicSharedMemorySize, SMEM_3BUF);
        attr_set = true;
    }

    pack_w        <<<576, 256>>>(qw, kvw, pw);
    cvt_x         <<<dim3(32, 128, 2), 256>>>(x);
    qkv_mma       <<<dim3(5, 256, 2), 256, SMEM_3BUF>>>(qb, kvb);
    scores_mma    <<<dim3(64, 16), 128>>>();
    softmax_kernel<<<16, 1024>>>();
    av_kernel     <<<dim3(32, 16), 256>>>();
    proj_mma      <<<dim3(2, 256, 2), 256, SMEM_3BUF>>>(pb, ls, out);
}